// round 5
// baseline (speedup 1.0000x reference)
#include <cuda_runtime.h>
#include <cuda_bf16.h>
#include <mma.h>
#include <math.h>
#include <cstdint>

using namespace nvcuda;
typedef __nv_bfloat16 bf;

#define NN 30000
#define NNP 30080
#define EE 300000
#define EEP 300032
#define HH 8
#define HID 256

// ===================== PTX helpers ==========================================
__device__ __forceinline__ uint32_t smem_u32(const void* p) {
    uint32_t a;
    asm("{ .reg .u64 t; cvta.to.shared.u64 t, %1; cvt.u32.u64 %0, t; }" : "=r"(a) : "l"(p));
    return a;
}
#define CP_ASYNC16(saddr, gptr) \
    asm volatile("cp.async.cg.shared.global [%0], [%1], 16;" :: "r"(saddr), "l"(gptr))
#define CP_COMMIT() asm volatile("cp.async.commit_group;" ::: "memory")
#define CP_WAIT(n)  asm volatile("cp.async.wait_group %0;" :: "n"(n) : "memory")

__device__ __forceinline__ void redAdd4(float* p, float a, float b, float c, float d) {
    asm volatile("red.global.add.v4.f32 [%0], {%1, %2, %3, %4};"
                 :: "l"(p), "f"(a), "f"(b), "f"(c), "f"(d) : "memory");
}

// ===================== scratch ==============================================
__device__ float g_q[NN * HID];
__device__ float g_k[NN * HID];
__device__ float g_v[NN * HID];
__device__ float g_skip[NN * HID];
__device__ float g_logits[EE * HH];
__device__ float g_m[NN * HH];
__device__ float g_denom[NN * HH];
__device__ float g_num[NN * HID];
__device__ float g_out[NN * HID];

__device__ bf g_xh[NNP * HID],   g_xl[NNP * HID];
__device__ bf g_outh[NNP * HID], g_outl[NNP * HID];
__device__ bf g_h1h[NNP * HID],  g_h1l[NNP * HID];
__device__ bf g_eah[EEP * 32],   g_eal[EEP * 32];    // pad rows stay 0 (zero-init)
__device__ bf g_w4h[256 * 1024], g_w4l[256 * 1024];  // [K=256][Wq|Wk|Wv|Wskip]
__device__ bf g_w1h[256 * 256],  g_w1l[256 * 256];
__device__ bf g_w2h[256 * 256],  g_w2l[256 * 256];
__device__ bf g_weh[32 * 256],   g_wel[32 * 256];
__device__ float g_b4[1024];

// ===================== scalar helpers =======================================
__device__ __forceinline__ float gelu_tanh(float x) {
    float x3 = x * x * x;
    float t = tanhf(0.7978845608028654f * (x + 0.044715f * x3));
    return 0.5f * x * (1.0f + t);
}
__device__ __forceinline__ void atomicMaxF(float* addr, float val) {
    if (val >= 0.0f) atomicMax(reinterpret_cast<int*>(addr), __float_as_int(val));
    else             atomicMin(reinterpret_cast<unsigned int*>(addr), __float_as_uint(val));
}
__device__ __forceinline__ void split2(float v, bf& h, bf& l) {
    h = __float2bfloat16(v);
    l = __float2bfloat16(v - __bfloat162float(h));
}

// ===================== conversion kernels ===================================
__global__ void cvt_split(const float* __restrict__ src, bf* __restrict__ h,
                          bf* __restrict__ l, int n) {
    int i = blockIdx.x * blockDim.x + threadIdx.x;
    if (i >= n) return;
    split2(src[i], h[i], l[i]);
}

#define W4_SZ   (256 * 1024)
#define W1_OFF  W4_SZ
#define W2_OFF  (W1_OFF + 65536)
#define WE_OFF  (W2_OFF + 65536)
#define B4_OFF  (WE_OFF + 8192)
#define CW_TOT  (B4_OFF + 1024)

__global__ void cvt_weights(const float* __restrict__ Wq, const float* __restrict__ Wk,
                            const float* __restrict__ Wv, const float* __restrict__ Ws,
                            const float* __restrict__ W1, const float* __restrict__ W2,
                            const float* __restrict__ We, const float* __restrict__ bq,
                            const float* __restrict__ bk, const float* __restrict__ bv) {
    int i = blockIdx.x * blockDim.x + threadIdx.x;
    if (i < W4_SZ) {
        int k = i >> 10, j = i & 1023, g = j >> 8, n = j & 255;
        const float* W = (g == 0) ? Wq : (g == 1) ? Wk : (g == 2) ? Wv : Ws;
        split2(W[k * 256 + n], g_w4h[i], g_w4l[i]);
    } else if (i < W2_OFF) {
        int t = i - W1_OFF; split2(W1[t], g_w1h[t], g_w1l[t]);
    } else if (i < WE_OFF) {
        int t = i - W2_OFF; split2(W2[t], g_w2h[t], g_w2l[t]);
    } else if (i < B4_OFF) {
        int t = i - WE_OFF; split2(We[t], g_weh[t], g_wel[t]);
    } else if (i < CW_TOT) {
        int t = i - B4_OFF, g = t >> 8, n = t & 255;
        g_b4[t] = (g == 0) ? bq[n] : (g == 1) ? bk[n] : (g == 2) ? bv[n] : 0.0f;
    }
}

// ===================== pipelined wmma GEMM (dense layers) ====================
static constexpr int APITCH = 72, BPITCH = 136;
static constexpr int ABYTES = 128 * APITCH * 2;
static constexpr int BBYTES = 64 * BPITCH * 2;

__device__ __forceinline__ void prefetch_tiles(
    uint32_t sbase, int Bbase,
    const bf* __restrict__ Ah, const bf* __restrict__ Al,
    const bf* __restrict__ Bh, const bf* __restrict__ Bl,
    int NTOT, int KF, int CHUNK, int row0, int n0, int c, int buf, int tid)
{
    const int CB = CHUNK / 8;
    const bf* Ag[2] = {Ah, Al};
    const bf* Bg[2] = {Bh, Bl};
#pragma unroll
    for (int hl = 0; hl < 2; hl++) {
        uint32_t sA = sbase + (uint32_t)(buf * 2 + hl) * ABYTES;
        const bf* srcA = Ag[hl] + (size_t)row0 * KF + c * CHUNK;
        for (int i = tid; i < 128 * CB; i += 256) {
            int r = i / CB, cc = i - r * CB;
            CP_ASYNC16(sA + r * (APITCH * 2) + cc * 16, srcA + (size_t)r * KF + cc * 8);
        }
        uint32_t sB = sbase + Bbase + (uint32_t)(buf * 2 + hl) * BBYTES;
        const bf* srcB = Bg[hl] + (size_t)(c * CHUNK) * NTOT + n0;
        for (int i = tid; i < CHUNK * 16; i += 256) {
            int r = i >> 4, cc = i & 15;
            CP_ASYNC16(sB + r * (BPITCH * 2) + cc * 16, srcB + (size_t)r * NTOT + cc * 8);
        }
    }
}

// EPI: 1 +bias f32 (4-way out split) | 2 +bias,gelu -> bf16 hi/lo | 3 +bias,gelu,+res -> f32
template <int KF, int EPI>
__global__ void __launch_bounds__(256) wgemm(
    const bf* __restrict__ Ah, const bf* __restrict__ Al,
    const bf* __restrict__ Bh, const bf* __restrict__ Bl, int NTOT,
    const float* __restrict__ bias, const float* __restrict__ res,
    float* __restrict__ O0, float* __restrict__ O1,
    float* __restrict__ O2, float* __restrict__ O3,
    bf* __restrict__ Ch, bf* __restrict__ Cl, int M)
{
    constexpr int CHUNK = (KF < 64) ? KF : 64;
    constexpr int NCH = KF / CHUNK;
    constexpr int NBUF = (NCH > 1) ? 2 : 1;
    constexpr int BBASE = NBUF * 2 * ABYTES;

    extern __shared__ char smem[];
    const uint32_t sbase = smem_u32(smem);

    int tid = threadIdx.x;
    int wid = tid >> 5;
    int mw = wid >> 1, nw = wid & 1;
    int n0 = blockIdx.x * 128;
    int row0 = blockIdx.y * 128;

    wmma::fragment<wmma::accumulator, 16, 16, 16, float> acc[2][4];
#pragma unroll
    for (int i = 0; i < 2; i++)
#pragma unroll
        for (int j = 0; j < 4; j++) wmma::fill_fragment(acc[i][j], 0.0f);

    prefetch_tiles(sbase, BBASE, Ah, Al, Bh, Bl, NTOT, KF, CHUNK, row0, n0, 0, 0, tid);
    CP_COMMIT();

#pragma unroll 1
    for (int c = 0; c < NCH; c++) {
        if (c + 1 < NCH) {
            prefetch_tiles(sbase, BBASE, Ah, Al, Bh, Bl, NTOT, KF, CHUNK, row0, n0,
                           c + 1, (c + 1) & 1, tid);
            CP_COMMIT();
            CP_WAIT(1);
        } else {
            CP_WAIT(0);
        }
        __syncthreads();

        int buf = (NBUF > 1) ? (c & 1) : 0;
        const bf* sAh = reinterpret_cast<const bf*>(smem + (size_t)(buf * 2 + 0) * ABYTES);
        const bf* sAl = reinterpret_cast<const bf*>(smem + (size_t)(buf * 2 + 1) * ABYTES);
        const bf* sBh = reinterpret_cast<const bf*>(smem + BBASE + (size_t)(buf * 2 + 0) * BBYTES);
        const bf* sBl = reinterpret_cast<const bf*>(smem + BBASE + (size_t)(buf * 2 + 1) * BBYTES);

#pragma unroll
        for (int ks = 0; ks < CHUNK / 16; ks++) {
            wmma::fragment<wmma::matrix_a, 16, 16, 16, bf, wmma::row_major> fah[2], fal[2];
            wmma::load_matrix_sync(fah[0], sAh + (mw * 32) * APITCH + ks * 16, APITCH);
            wmma::load_matrix_sync(fah[1], sAh + (mw * 32 + 16) * APITCH + ks * 16, APITCH);
            wmma::load_matrix_sync(fal[0], sAl + (mw * 32) * APITCH + ks * 16, APITCH);
            wmma::load_matrix_sync(fal[1], sAl + (mw * 32 + 16) * APITCH + ks * 16, APITCH);
#pragma unroll
            for (int j = 0; j < 4; j++) {
                wmma::fragment<wmma::matrix_b, 16, 16, 16, bf, wmma::row_major> fbh, fbl;
                wmma::load_matrix_sync(fbh, sBh + (ks * 16) * BPITCH + nw * 64 + j * 16, BPITCH);
                wmma::load_matrix_sync(fbl, sBl + (ks * 16) * BPITCH + nw * 64 + j * 16, BPITCH);
#pragma unroll
                for (int i = 0; i < 2; i++) {
                    wmma::mma_sync(acc[i][j], fah[i], fbh, acc[i][j]);
                    wmma::mma_sync(acc[i][j], fah[i], fbl, acc[i][j]);
                    wmma::mma_sync(acc[i][j], fal[i], fbh, acc[i][j]);
                }
            }
        }
        __syncthreads();
    }

    float* stage = reinterpret_cast<float*>(smem);
    {
        int base = (mw * 32) * 132 + nw * 64;
#pragma unroll
        for (int i = 0; i < 2; i++)
#pragma unroll
            for (int j = 0; j < 4; j++)
                wmma::store_matrix_sync(stage + base + i * 16 * 132 + j * 16,
                                        acc[i][j], 132, wmma::mem_row_major);
    }
    __syncthreads();

    float* Of = O0;
    if (EPI != 2) {
        int which = n0 >> 8;
        Of = (which == 0) ? O0 : (which == 1) ? O1 : (which == 2) ? O2 : O3;
    }
    int cb0 = n0 & 255;

    for (int i = tid; i < 128 * 32; i += 256) {
        int r = i >> 5, c4 = i & 31;
        int grow = row0 + r;
        if (grow >= M) continue;
        float4 v = *reinterpret_cast<float4*>(stage + r * 132 + c4 * 4);
        if (EPI >= 1) {
            const float* bp = bias + n0 + c4 * 4;
            v.x += bp[0]; v.y += bp[1]; v.z += bp[2]; v.w += bp[3];
        }
        if (EPI >= 2) {
            v.x = gelu_tanh(v.x); v.y = gelu_tanh(v.y);
            v.z = gelu_tanh(v.z); v.w = gelu_tanh(v.w);
        }
        size_t idx = (size_t)grow * 256 + cb0 + c4 * 4;
        if (EPI == 2) {
            bf h0, l0, h1, l1, h2, l2, h3, l3;
            split2(v.x, h0, l0); split2(v.y, h1, l1);
            split2(v.z, h2, l2); split2(v.w, h3, l3);
            __nv_bfloat162 hh0{h0, h1}, hh1{h2, h3}, ll0{l0, l1}, ll1{l2, l3};
            *reinterpret_cast<__nv_bfloat162*>(Ch + idx)     = hh0;
            *reinterpret_cast<__nv_bfloat162*>(Ch + idx + 2) = hh1;
            *reinterpret_cast<__nv_bfloat162*>(Cl + idx)     = ll0;
            *reinterpret_cast<__nv_bfloat162*>(Cl + idx + 2) = ll1;
        } else {
            if (EPI == 3) {
                float4 rr = *reinterpret_cast<const float4*>(res + idx);
                v.x += rr.x; v.y += rr.y; v.z += rr.z; v.w += rr.w;
            }
            *reinterpret_cast<float4*>(Of + idx) = v;
        }
    }
}

// ===================== fused edge passes ====================================
// CTA = 64 edges. smem: estage f32[64][256] | We hi/lo bf16[32][256] | EA hi/lo bf16[64][32]
#define ES_WEH 65536
#define ES_WEL 81920
#define ES_EAH 98304
#define ES_EAL 102400
#define ES_TOT 106496

__device__ __forceinline__ void load_edge_tiles(uint32_t sb, int e0, int tid) {
    const char* weh = reinterpret_cast<const char*>(g_weh);
    const char* wel = reinterpret_cast<const char*>(g_wel);
    for (int i = tid; i < 1024; i += 256) {
        CP_ASYNC16(sb + ES_WEH + i * 16, weh + i * 16);
        CP_ASYNC16(sb + ES_WEL + i * 16, wel + i * 16);
    }
    const char* eah = reinterpret_cast<const char*>(g_eah + (size_t)e0 * 32);
    const char* eal = reinterpret_cast<const char*>(g_eal + (size_t)e0 * 32);
    CP_ASYNC16(sb + ES_EAH + tid * 16, eah + tid * 16);
    CP_ASYNC16(sb + ES_EAL + tid * 16, eal + tid * 16);
    CP_COMMIT();
}

// 64x256 (K=32) 3-term GEMM into estage. 8 warps: (2m x 4n), warp tile 32x64.
__device__ __forceinline__ void compute_e_tile(char* smem, int tid) {
    float* estage = reinterpret_cast<float*>(smem);
    const bf* Weh = reinterpret_cast<const bf*>(smem + ES_WEH);
    const bf* Wel = reinterpret_cast<const bf*>(smem + ES_WEL);
    const bf* EAh = reinterpret_cast<const bf*>(smem + ES_EAH);
    const bf* EAl = reinterpret_cast<const bf*>(smem + ES_EAL);
    int wid = tid >> 5;
    int mw = wid >> 2, nw = wid & 3;

    wmma::fragment<wmma::accumulator, 16, 16, 16, float> acc[2][4];
#pragma unroll
    for (int i = 0; i < 2; i++)
#pragma unroll
        for (int j = 0; j < 4; j++) wmma::fill_fragment(acc[i][j], 0.0f);

#pragma unroll
    for (int ks = 0; ks < 2; ks++) {
        wmma::fragment<wmma::matrix_a, 16, 16, 16, bf, wmma::row_major> fah[2], fal[2];
        wmma::load_matrix_sync(fah[0], EAh + (mw * 32) * 32 + ks * 16, 32);
        wmma::load_matrix_sync(fah[1], EAh + (mw * 32 + 16) * 32 + ks * 16, 32);
        wmma::load_matrix_sync(fal[0], EAl + (mw * 32) * 32 + ks * 16, 32);
        wmma::load_matrix_sync(fal[1], EAl + (mw * 32 + 16) * 32 + ks * 16, 32);
#pragma unroll
        for (int j = 0; j < 4; j++) {
            wmma::fragment<wmma::matrix_b, 16, 16, 16, bf, wmma::row_major> fbh, fbl;
            wmma::load_matrix_sync(fbh, Weh + (ks * 16) * 256 + nw * 64 + j * 16, 256);
            wmma::load_matrix_sync(fbl, Wel + (ks * 16) * 256 + nw * 64 + j * 16, 256);
#pragma unroll
            for (int i = 0; i < 2; i++) {
                wmma::mma_sync(acc[i][j], fah[i], fbh, acc[i][j]);
                wmma::mma_sync(acc[i][j], fah[i], fbl, acc[i][j]);
                wmma::mma_sync(acc[i][j], fal[i], fbh, acc[i][j]);
            }
        }
    }
#pragma unroll
    for (int i = 0; i < 2; i++)
#pragma unroll
        for (int j = 0; j < 4; j++)
            wmma::store_matrix_sync(estage + (mw * 32 + i * 16) * 256 + nw * 64 + j * 16,
                                    acc[i][j], 256, wmma::mem_row_major);
}

__global__ void __launch_bounds__(256) edge_pass_a(const int* __restrict__ ei) {
    extern __shared__ char smem[];
    uint32_t sb = smem_u32(smem);
    int tid = threadIdx.x, wid = tid >> 5, lane = tid & 31;
    int e0 = blockIdx.x * 64;

    load_edge_tiles(sb, e0, tid);
    CP_WAIT(0);
    __syncthreads();
    compute_e_tile(smem, tid);
    __syncthreads();

    const float* estage = reinterpret_cast<const float*>(smem);
#pragma unroll 2
    for (int i = 0; i < 8; i++) {
        int er = wid * 8 + i;
        int eidx = e0 + er;
        if (eidx >= EE) break;
        int src = __ldg(ei + eidx);
        int dst = __ldg(ei + EE + eidx);
        const float* qrow = g_q + (size_t)dst * 256;
        const float* krow = g_k + (size_t)src * 256;
        const float* erow = estage + er * 256;
        float s[8];
#pragma unroll
        for (int h = 0; h < 8; h++) {
            int j = h * 32 + lane;
            s[h] = qrow[j] * (krow[j] + erow[j]);
        }
#pragma unroll
        for (int off = 16; off; off >>= 1)
#pragma unroll
            for (int h = 0; h < 8; h++) s[h] += __shfl_xor_sync(0xffffffffu, s[h], off);
        if (lane < 8) {
            float lg = s[lane] * 0.17677669529663687f;
            g_logits[(size_t)eidx * 8 + lane] = lg;
            atomicMaxF(&g_m[dst * 8 + lane], lg);
        }
    }
}

__global__ void __launch_bounds__(256) edge_pass_b(const int* __restrict__ ei) {
    extern __shared__ char smem[];
    uint32_t sb = smem_u32(smem);
    int tid = threadIdx.x, wid = tid >> 5, lane = tid & 31;
    int e0 = blockIdx.x * 64;

    load_edge_tiles(sb, e0, tid);
    CP_WAIT(0);
    __syncthreads();
    compute_e_tile(smem, tid);
    __syncthreads();

    const float* estage = reinterpret_cast<const float*>(smem);
#pragma unroll 2
    for (int i = 0; i < 8; i++) {
        int er = wid * 8 + i;
        int eidx = e0 + er;
        if (eidx >= EE) break;
        int src = __ldg(ei + eidx);
        int dst = __ldg(ei + EE + eidx);
        float a = 0.0f;
        if (lane < 8) {
            a = expf(g_logits[(size_t)eidx * 8 + lane] - g_m[dst * 8 + lane]);
            atomicAdd(&g_denom[dst * 8 + lane], a);
        }
        float ah[8];
#pragma unroll
        for (int h = 0; h < 8; h++) ah[h] = __shfl_sync(0xffffffffu, a, h);

        const float4* v4 = reinterpret_cast<const float4*>(g_v + (size_t)src * 256);
        const float4* e4 = reinterpret_cast<const float4*>(estage + er * 256);
        float* nrow = g_num + (size_t)dst * 256;
#pragma unroll
        for (int half = 0; half < 2; half++) {
            int col4 = half * 32 + lane;
            float al = ah[col4 >> 3];
            float4 vv = v4[col4];
            float4 ee = e4[col4];
            redAdd4(nrow + col4 * 4,
                    (vv.x + ee.x) * al, (vv.y + ee.y) * al,
                    (vv.z + ee.z) * al, (vv.w + ee.w) * al);
        }
    }
}

// ===================== node kernels =========================================
__global__ void init_kernel() {
    int i = blockIdx.x * blockDim.x + threadIdx.x;
    if (i < NN * HH) { g_m[i] = -INFINITY; g_denom[i] = 0.0f; }
    if (i < NN * HID) g_num[i] = 0.0f;
}

__global__ void node_out_kernel() {
    int i = blockIdx.x * blockDim.x + threadIdx.x;
    if (i >= NN * HID) return;
    int n = i >> 8;
    int h = (i & 255) >> 5;
    float o = g_num[i] / (g_denom[n * 8 + h] + 1e-16f) + g_skip[i];
    g_out[i] = o;
    split2(o, g_outh[i], g_outl[i]);
}

// ===================== launch ===============================================
extern "C" void kernel_launch(void* const* d_in, const int* in_sizes, int n_in,
                              void* d_out, int out_size) {
    const float* x         = (const float*)d_in[0];
    const int*   edge_idx  = (const int*)d_in[1];
    const float* edge_attr = (const float*)d_in[2];
    const float* Wq = (const float*)d_in[3];
    const float* bq = (const float*)d_in[4];
    const float* Wk = (const float*)d_in[5];
    const float* bk = (const float*)d_in[6];
    const float* Wv = (const float*)d_in[7];
    const float* bv = (const float*)d_in[8];
    const float* We = (const float*)d_in[9];
    const float* Wskip = (const float*)d_in[10];
    const float* W1 = (const float*)d_in[11];
    const float* b1 = (const float*)d_in[12];
    const float* W2 = (const float*)d_in[13];
    const float* b2 = (const float*)d_in[14];

    void *pq, *pk, *pv, *pskip, *pout;
    void *pxh, *pxl, *pouth, *poutl, *ph1h, *ph1l, *peah, *peal;
    void *pw4h, *pw4l, *pw1h, *pw1l, *pw2h, *pw2l, *pb4;
    cudaGetSymbolAddress(&pq, g_q);       cudaGetSymbolAddress(&pk, g_k);
    cudaGetSymbolAddress(&pv, g_v);       cudaGetSymbolAddress(&pskip, g_skip);
    cudaGetSymbolAddress(&pout, g_out);
    cudaGetSymbolAddress(&pxh, g_xh);     cudaGetSymbolAddress(&pxl, g_xl);
    cudaGetSymbolAddress(&pouth, g_outh); cudaGetSymbolAddress(&poutl, g_outl);
    cudaGetSymbolAddress(&ph1h, g_h1h);   cudaGetSymbolAddress(&ph1l, g_h1l);
    cudaGetSymbolAddress(&peah, g_eah);   cudaGetSymbolAddress(&peal, g_eal);
    cudaGetSymbolAddress(&pw4h, g_w4h);   cudaGetSymbolAddress(&pw4l, g_w4l);
    cudaGetSymbolAddress(&pw1h, g_w1h);   cudaGetSymbolAddress(&pw1l, g_w1l);
    cudaGetSymbolAddress(&pw2h, g_w2h);   cudaGetSymbolAddress(&pw2l, g_w2l);
    cudaGetSymbolAddress(&pb4, g_b4);

    const int SMEM_BIG = 2 * 2 * (ABYTES + BBYTES);
    cudaFuncSetAttribute(wgemm<256,1>, cudaFuncAttributeMaxDynamicSharedMemorySize, SMEM_BIG);
    cudaFuncSetAttribute(wgemm<256,2>, cudaFuncAttributeMaxDynamicSharedMemorySize, SMEM_BIG);
    cudaFuncSetAttribute(wgemm<256,3>, cudaFuncAttributeMaxDynamicSharedMemorySize, SMEM_BIG);
    cudaFuncSetAttribute(edge_pass_a, cudaFuncAttributeMaxDynamicSharedMemorySize, ES_TOT);
    cudaFuncSetAttribute(edge_pass_b, cudaFuncAttributeMaxDynamicSharedMemorySize, ES_TOT);

    init_kernel<<<(NN * HID + 255) / 256, 256>>>();
    cvt_weights<<<(CW_TOT + 255) / 256, 256>>>(Wq, Wk, Wv, Wskip, W1, W2, We,
                                               bq, bk, bv);
    cvt_split<<<(NN * HID + 255) / 256, 256>>>(x, (bf*)pxh, (bf*)pxl, NN * HID);
    cvt_split<<<(EE * 32 + 255) / 256, 256>>>(edge_attr, (bf*)peah, (bf*)peal, EE * 32);

    // fused QKVS  [NNP x 256] @ [256 x 1024]
    wgemm<256,1><<<dim3(8, NNP / 128), 256, SMEM_BIG>>>(
        (bf*)pxh, (bf*)pxl, (bf*)pw4h, (bf*)pw4l, 1024,
        (const float*)pb4, nullptr,
        (float*)pq, (float*)pk, (float*)pv, (float*)pskip, nullptr, nullptr, NN);

    // fused edge passes (e recomputed in-CTA, never materialized)
    edge_pass_a<<<EEP / 64, 256, ES_TOT>>>(edge_idx);
    edge_pass_b<<<EEP / 64, 256, ES_TOT>>>(edge_idx);
    node_out_kernel<<<(NN * HID + 255) / 256, 256>>>();

    // MLP
    wgemm<256,2><<<dim3(2, NNP / 128), 256, SMEM_BIG>>>(
        (bf*)pouth, (bf*)poutl, (bf*)pw1h, (bf*)pw1l, 256,
        b1, nullptr, nullptr, nullptr, nullptr, nullptr,
        (bf*)ph1h, (bf*)ph1l, NN);
    wgemm<256,3><<<dim3(2, NNP / 128), 256, SMEM_BIG>>>(
        (bf*)ph1h, (bf*)ph1l, (bf*)pw2h, (bf*)pw2l, 256,
        b2, (const float*)pout, (float*)d_out, nullptr, nullptr, nullptr,
        nullptr, nullptr, NN);
}

// round 6
// speedup vs baseline: 1.6509x; 1.6509x over previous
#include <cuda_runtime.h>
#include <cuda_bf16.h>
#include <mma.h>
#include <math.h>
#include <cstdint>

using namespace nvcuda;
typedef __nv_bfloat16 bf;

#define NN 30000
#define NNP 30080
#define EE 300000
#define HH 8
#define HID 256

// ===================== PTX helpers ==========================================
__device__ __forceinline__ uint32_t smem_u32(const void* p) {
    uint32_t a;
    asm("{ .reg .u64 t; cvta.to.shared.u64 t, %1; cvt.u32.u64 %0, t; }" : "=r"(a) : "l"(p));
    return a;
}
#define CP_ASYNC16(saddr, gptr) \
    asm volatile("cp.async.cg.shared.global [%0], [%1], 16;" :: "r"(saddr), "l"(gptr))
#define CP_COMMIT() asm volatile("cp.async.commit_group;" ::: "memory")
#define CP_WAIT(n)  asm volatile("cp.async.wait_group %0;" :: "n"(n) : "memory")

// ===================== scratch ==============================================
__device__ float g_q[NN * HID];
__device__ float g_k[NN * HID];
__device__ float g_v[NN * HID];
__device__ float g_skip[NN * HID];
__device__ float g_G[NN * HID];        // G[n, d, h] = sum_c We[d,h*32+c] q[n,h*32+c]
__device__ float g_logits[EE * HH];
__device__ float g_out[NN * HID];

__device__ int g_deg[NN];
__device__ int g_pos[NN];
__device__ int g_off[NN + 1];
__device__ int g_eid[EE];

__device__ bf g_xh[NNP * HID],   g_xl[NNP * HID];
__device__ bf g_outh[NNP * HID], g_outl[NNP * HID];   // pad rows stay 0
__device__ bf g_h1h[NNP * HID],  g_h1l[NNP * HID];
__device__ bf g_w4h[256 * 1024], g_w4l[256 * 1024];   // [K=256][Wq|Wk|Wv|Wskip]
__device__ bf g_w1h[256 * 256],  g_w1l[256 * 256];
__device__ bf g_w2h[256 * 256],  g_w2l[256 * 256];
__device__ float g_b4[1024];

// ===================== scalar helpers =======================================
__device__ __forceinline__ float gelu_tanh(float x) {
    float x3 = x * x * x;
    float t = tanhf(0.7978845608028654f * (x + 0.044715f * x3));
    return 0.5f * x * (1.0f + t);
}
__device__ __forceinline__ void split2(float v, bf& h, bf& l) {
    h = __float2bfloat16(v);
    l = __float2bfloat16(v - __bfloat162float(h));
}

// ===================== conversion kernels ===================================
__global__ void cvt_split(const float* __restrict__ src, bf* __restrict__ h,
                          bf* __restrict__ l, int n) {
    int i = blockIdx.x * blockDim.x + threadIdx.x;
    if (i >= n) return;
    float v = src[i];
    bf hh = __float2bfloat16(v);
    h[i] = hh;
    l[i] = __float2bfloat16(v - __bfloat162float(hh));
}

#define W4_SZ   (256 * 1024)
#define W1_OFF  W4_SZ
#define W2_OFF  (W1_OFF + 65536)
#define B4_OFF  (W2_OFF + 65536)
#define CW_TOT  (B4_OFF + 1024)

__global__ void cvt_weights(const float* __restrict__ Wq, const float* __restrict__ Wk,
                            const float* __restrict__ Wv, const float* __restrict__ Ws,
                            const float* __restrict__ W1, const float* __restrict__ W2,
                            const float* __restrict__ bq, const float* __restrict__ bk,
                            const float* __restrict__ bv) {
    int i = blockIdx.x * blockDim.x + threadIdx.x;
    if (i < W4_SZ) {
        int k = i >> 10, j = i & 1023, g = j >> 8, n = j & 255;
        const float* W = (g == 0) ? Wq : (g == 1) ? Wk : (g == 2) ? Wv : Ws;
        split2(W[k * 256 + n], g_w4h[i], g_w4l[i]);
    } else if (i < W2_OFF) {
        int t = i - W1_OFF; split2(W1[t], g_w1h[t], g_w1l[t]);
    } else if (i < B4_OFF) {
        int t = i - W2_OFF; split2(W2[t], g_w2h[t], g_w2l[t]);
    } else if (i < CW_TOT) {
        int t = i - B4_OFF, g = t >> 8, n = t & 255;
        g_b4[t] = (g == 0) ? bq[n] : (g == 1) ? bk[n] : (g == 2) ? bv[n] : 0.0f;
    }
}

// ===================== pipelined wmma GEMM (unchanged from R4) ===============
static constexpr int APITCH = 72, BPITCH = 136;
static constexpr int ABYTES = 128 * APITCH * 2;
static constexpr int BBYTES = 64 * BPITCH * 2;

__device__ __forceinline__ void prefetch_tiles(
    uint32_t sbase, int Bbase,
    const bf* __restrict__ Ah, const bf* __restrict__ Al,
    const bf* __restrict__ Bh, const bf* __restrict__ Bl,
    int NTOT, int KF, int CHUNK, int row0, int n0, int c, int buf, int tid)
{
    const int CB = CHUNK / 8;
    const bf* Ag[2] = {Ah, Al};
    const bf* Bg[2] = {Bh, Bl};
#pragma unroll
    for (int hl = 0; hl < 2; hl++) {
        uint32_t sA = sbase + (uint32_t)(buf * 2 + hl) * ABYTES;
        const bf* srcA = Ag[hl] + (size_t)row0 * KF + c * CHUNK;
        for (int i = tid; i < 128 * CB; i += 256) {
            int r = i / CB, cc = i - r * CB;
            CP_ASYNC16(sA + r * (APITCH * 2) + cc * 16, srcA + (size_t)r * KF + cc * 8);
        }
        uint32_t sB = sbase + Bbase + (uint32_t)(buf * 2 + hl) * BBYTES;
        const bf* srcB = Bg[hl] + (size_t)(c * CHUNK) * NTOT + n0;
        for (int i = tid; i < CHUNK * 16; i += 256) {
            int r = i >> 4, cc = i & 15;
            CP_ASYNC16(sB + r * (BPITCH * 2) + cc * 16, srcB + (size_t)r * NTOT + cc * 8);
        }
    }
}

// EPI: 1 +bias f32 (4-way out split) | 2 +bias,gelu -> bf16 hi/lo | 3 +bias,gelu,+res -> f32
template <int KF, int EPI>
__global__ void __launch_bounds__(256) wgemm(
    const bf* __restrict__ Ah, const bf* __restrict__ Al,
    const bf* __restrict__ Bh, const bf* __restrict__ Bl, int NTOT,
    const float* __restrict__ bias, const float* __restrict__ res,
    float* __restrict__ O0, float* __restrict__ O1,
    float* __restrict__ O2, float* __restrict__ O3,
    bf* __restrict__ Ch, bf* __restrict__ Cl, int M)
{
    constexpr int CHUNK = (KF < 64) ? KF : 64;
    constexpr int NCH = KF / CHUNK;
    constexpr int NBUF = (NCH > 1) ? 2 : 1;
    constexpr int BBASE = NBUF * 2 * ABYTES;

    extern __shared__ char smem[];
    const uint32_t sbase = smem_u32(smem);

    int tid = threadIdx.x;
    int wid = tid >> 5;
    int mw = wid >> 1, nw = wid & 1;
    int n0 = blockIdx.x * 128;
    int row0 = blockIdx.y * 128;

    wmma::fragment<wmma::accumulator, 16, 16, 16, float> acc[2][4];
#pragma unroll
    for (int i = 0; i < 2; i++)
#pragma unroll
        for (int j = 0; j < 4; j++) wmma::fill_fragment(acc[i][j], 0.0f);

    prefetch_tiles(sbase, BBASE, Ah, Al, Bh, Bl, NTOT, KF, CHUNK, row0, n0, 0, 0, tid);
    CP_COMMIT();

#pragma unroll 1
    for (int c = 0; c < NCH; c++) {
        if (c + 1 < NCH) {
            prefetch_tiles(sbase, BBASE, Ah, Al, Bh, Bl, NTOT, KF, CHUNK, row0, n0,
                           c + 1, (c + 1) & 1, tid);
            CP_COMMIT();
            CP_WAIT(1);
        } else {
            CP_WAIT(0);
        }
        __syncthreads();

        int buf = (NBUF > 1) ? (c & 1) : 0;
        const bf* sAh = reinterpret_cast<const bf*>(smem + (size_t)(buf * 2 + 0) * ABYTES);
        const bf* sAl = reinterpret_cast<const bf*>(smem + (size_t)(buf * 2 + 1) * ABYTES);
        const bf* sBh = reinterpret_cast<const bf*>(smem + BBASE + (size_t)(buf * 2 + 0) * BBYTES);
        const bf* sBl = reinterpret_cast<const bf*>(smem + BBASE + (size_t)(buf * 2 + 1) * BBYTES);

#pragma unroll
        for (int ks = 0; ks < CHUNK / 16; ks++) {
            wmma::fragment<wmma::matrix_a, 16, 16, 16, bf, wmma::row_major> fah[2], fal[2];
            wmma::load_matrix_sync(fah[0], sAh + (mw * 32) * APITCH + ks * 16, APITCH);
            wmma::load_matrix_sync(fah[1], sAh + (mw * 32 + 16) * APITCH + ks * 16, APITCH);
            wmma::load_matrix_sync(fal[0], sAl + (mw * 32) * APITCH + ks * 16, APITCH);
            wmma::load_matrix_sync(fal[1], sAl + (mw * 32 + 16) * APITCH + ks * 16, APITCH);
#pragma unroll
            for (int j = 0; j < 4; j++) {
                wmma::fragment<wmma::matrix_b, 16, 16, 16, bf, wmma::row_major> fbh, fbl;
                wmma::load_matrix_sync(fbh, sBh + (ks * 16) * BPITCH + nw * 64 + j * 16, BPITCH);
                wmma::load_matrix_sync(fbl, sBl + (ks * 16) * BPITCH + nw * 64 + j * 16, BPITCH);
#pragma unroll
                for (int i = 0; i < 2; i++) {
                    wmma::mma_sync(acc[i][j], fah[i], fbh, acc[i][j]);
                    wmma::mma_sync(acc[i][j], fah[i], fbl, acc[i][j]);
                    wmma::mma_sync(acc[i][j], fal[i], fbh, acc[i][j]);
                }
            }
        }
        __syncthreads();
    }

    float* stage = reinterpret_cast<float*>(smem);
    {
        int base = (mw * 32) * 132 + nw * 64;
#pragma unroll
        for (int i = 0; i < 2; i++)
#pragma unroll
            for (int j = 0; j < 4; j++)
                wmma::store_matrix_sync(stage + base + i * 16 * 132 + j * 16,
                                        acc[i][j], 132, wmma::mem_row_major);
    }
    __syncthreads();

    float* Of = O0;
    if (EPI != 2) {
        int which = n0 >> 8;
        Of = (which == 0) ? O0 : (which == 1) ? O1 : (which == 2) ? O2 : O3;
    }
    int cb0 = n0 & 255;

    for (int i = tid; i < 128 * 32; i += 256) {
        int r = i >> 5, c4 = i & 31;
        int grow = row0 + r;
        if (grow >= M) continue;
        float4 v = *reinterpret_cast<float4*>(stage + r * 132 + c4 * 4);
        if (EPI >= 1) {
            const float* bp = bias + n0 + c4 * 4;
            v.x += bp[0]; v.y += bp[1]; v.z += bp[2]; v.w += bp[3];
        }
        if (EPI >= 2) {
            v.x = gelu_tanh(v.x); v.y = gelu_tanh(v.y);
            v.z = gelu_tanh(v.z); v.w = gelu_tanh(v.w);
        }
        size_t idx = (size_t)grow * 256 + cb0 + c4 * 4;
        if (EPI == 2) {
            bf h0, l0, h1, l1, h2, l2, h3, l3;
            split2(v.x, h0, l0); split2(v.y, h1, l1);
            split2(v.z, h2, l2); split2(v.w, h3, l3);
            __nv_bfloat162 hh0{h0, h1}, hh1{h2, h3}, ll0{l0, l1}, ll1{l2, l3};
            *reinterpret_cast<__nv_bfloat162*>(Ch + idx)     = hh0;
            *reinterpret_cast<__nv_bfloat162*>(Ch + idx + 2) = hh1;
            *reinterpret_cast<__nv_bfloat162*>(Cl + idx)     = ll0;
            *reinterpret_cast<__nv_bfloat162*>(Cl + idx + 2) = ll1;
        } else {
            if (EPI == 3) {
                float4 rr = *reinterpret_cast<const float4*>(res + idx);
                v.x += rr.x; v.y += rr.y; v.z += rr.z; v.w += rr.w;
            }
            *reinterpret_cast<float4*>(Of + idx) = v;
        }
    }
}

// ===================== CSR build ============================================
__global__ void init_kernel() {
    int i = blockIdx.x * blockDim.x + threadIdx.x;
    if (i < NN) { g_deg[i] = 0; g_pos[i] = 0; }
}
__global__ void hist_kernel(const int* __restrict__ ei) {
    int e = blockIdx.x * blockDim.x + threadIdx.x;
    if (e >= EE) return;
    atomicAdd(&g_deg[ei[EE + e]], 1);
}
__global__ void scan_kernel() {
    __shared__ int s[1024];
    __shared__ int carry;
    int t = threadIdx.x;
    if (t == 0) { carry = 0; g_off[0] = 0; }
    __syncthreads();
    for (int base = 0; base < NN; base += 1024) {
        int i = base + t;
        int v = (i < NN) ? g_deg[i] : 0;
        s[t] = v;
        __syncthreads();
#pragma unroll
        for (int d = 1; d < 1024; d <<= 1) {
            int tmp = (t >= d) ? s[t - d] : 0;
            __syncthreads();
            s[t] += tmp;
            __syncthreads();
        }
        if (i < NN) g_off[i + 1] = s[t] + carry;
        __syncthreads();
        if (t == 1023) carry += s[1023];
        __syncthreads();
    }
}
__global__ void scatter_kernel(const int* __restrict__ ei) {
    int e = blockIdx.x * blockDim.x + threadIdx.x;
    if (e >= EE) return;
    int dst = ei[EE + e];
    int p = atomicAdd(&g_pos[dst], 1);
    g_eid[g_off[dst] + p] = e;
}

// ===================== G precompute: G[n,d,h] = sum_c We[d,hc] q[n,hc] ======
__global__ void __launch_bounds__(256) g_kernel(const float* __restrict__ We) {
    __shared__ float sWe[32 * 257];
    __shared__ float sq[8][257];
    int tid = threadIdx.x, wid = tid >> 5, lane = tid & 31;
    for (int i = tid; i < 8192; i += 256) {
        int d = i >> 8, j = i & 255;
        sWe[d * 257 + j] = We[i];
    }
    int n = blockIdx.x * 8 + wid;
    bool valid = n < NN;
    if (valid) {
#pragma unroll
        for (int h = 0; h < 8; h++)
            sq[wid][h * 32 + lane] = g_q[(size_t)n * 256 + h * 32 + lane];
    }
    __syncthreads();
    if (!valid) return;
    float out[8];
#pragma unroll
    for (int h = 0; h < 8; h++) {
        float acc = 0.0f;
#pragma unroll
        for (int c = 0; c < 32; c++)
            acc += sWe[lane * 257 + h * 32 + c] * sq[wid][h * 32 + c];
        out[h] = acc;
    }
#pragma unroll
    for (int h = 0; h < 8; h++)
        g_G[(size_t)n * 256 + lane * 8 + h] = out[h];
}

// ===================== fused attention (warp per dst node) =================
__global__ void __launch_bounds__(256) attn_kernel(const int* __restrict__ ei,
                                                   const float* __restrict__ ea,
                                                   const float* __restrict__ We) {
    __shared__ float sWe[32 * 256];
    int tid = threadIdx.x, wid = tid >> 5, lane = tid & 31;
    for (int i = tid; i < 8192; i += 256) sWe[i] = We[i];
    __syncthreads();

    int n = blockIdx.x * 8 + wid;
    if (n >= NN) return;

    float qreg[8], Greg[8];
#pragma unroll
    for (int h = 0; h < 8; h++) {
        qreg[h] = g_q[(size_t)n * 256 + h * 32 + lane];
        Greg[h] = g_G[(size_t)n * 256 + lane * 8 + h];
    }

    int off0 = g_off[n];
    int deg = g_off[n + 1] - off0;
    const float scale = 0.17677669529663687f;  // 1/sqrt(32)

    // ---- pass 1: logits + per-head running max (registers) ----
    float m[8];
#pragma unroll
    for (int h = 0; h < 8; h++) m[h] = -INFINITY;

    for (int i = 0; i < deg; i++) {
        int eid = g_eid[off0 + i];
        int src = ei[eid];
        float ea_l = ea[(size_t)eid * 32 + lane];
        const float* krow = g_k + (size_t)src * 256;
        float s[8];
#pragma unroll
        for (int h = 0; h < 8; h++)
            s[h] = qreg[h] * krow[h * 32 + lane] + ea_l * Greg[h];
#pragma unroll
        for (int o = 16; o; o >>= 1)
#pragma unroll
            for (int h = 0; h < 8; h++) s[h] += __shfl_xor_sync(0xffffffffu, s[h], o);
#pragma unroll
        for (int h = 0; h < 8; h++) {
            s[h] *= scale;
            m[h] = fmaxf(m[h], s[h]);
        }
        if (lane < 8) g_logits[(size_t)eid * 8 + lane] = s[lane];
    }
    __syncwarp();

    // ---- pass 2: exp, denom, alpha*v, alpha*ea — all in registers ----
    float acc[8], den[8], wea[8];
#pragma unroll
    for (int h = 0; h < 8; h++) { acc[h] = 0.0f; den[h] = 0.0f; wea[h] = 0.0f; }

    int hm = lane & 7;
    for (int i = 0; i < deg; i++) {
        int eid = g_eid[off0 + i];
        int src = ei[eid];
        float lg = g_logits[(size_t)eid * 8 + hm];
        float a = __expf(lg - m[hm]);
        float ah[8];
#pragma unroll
        for (int h = 0; h < 8; h++) ah[h] = __shfl_sync(0xffffffffu, a, h);
        float ea_l = ea[(size_t)eid * 32 + lane];
        const float* vrow = g_v + (size_t)src * 256;
#pragma unroll
        for (int h = 0; h < 8; h++) {
            den[h] += ah[h];
            acc[h] += ah[h] * vrow[h * 32 + lane];
            wea[h] += ah[h] * ea_l;
        }
    }

    // ---- epilogue: + (wea @ We), divide, skip, write + bf16 split ----
#pragma unroll
    for (int h = 0; h < 8; h++) {
        float extra = 0.0f;
#pragma unroll
        for (int d = 0; d < 32; d++) {
            float w_hd = __shfl_sync(0xffffffffu, wea[h], d);
            extra += w_hd * sWe[d * 256 + h * 32 + lane];
        }
        size_t idx = (size_t)n * 256 + h * 32 + lane;
        float o = (acc[h] + extra) / (den[h] + 1e-16f) + g_skip[idx];
        g_out[idx] = o;
        bf oh, ol;
        split2(o, oh, ol);
        g_outh[idx] = oh;
        g_outl[idx] = ol;
    }
}

// ===================== launch ===============================================
extern "C" void kernel_launch(void* const* d_in, const int* in_sizes, int n_in,
                              void* d_out, int out_size) {
    const float* x         = (const float*)d_in[0];
    const int*   edge_idx  = (const int*)d_in[1];
    const float* edge_attr = (const float*)d_in[2];
    const float* Wq = (const float*)d_in[3];
    const float* bq = (const float*)d_in[4];
    const float* Wk = (const float*)d_in[5];
    const float* bk = (const float*)d_in[6];
    const float* Wv = (const float*)d_in[7];
    const float* bv = (const float*)d_in[8];
    const float* We = (const float*)d_in[9];
    const float* Wskip = (const float*)d_in[10];
    const float* W1 = (const float*)d_in[11];
    const float* b1 = (const float*)d_in[12];
    const float* W2 = (const float*)d_in[13];
    const float* b2 = (const float*)d_in[14];

    void *pq, *pk, *pv, *pskip, *pout;
    void *pxh, *pxl, *pouth, *poutl, *ph1h, *ph1l;
    void *pw4h, *pw4l, *pw1h, *pw1l, *pw2h, *pw2l, *pb4;
    cudaGetSymbolAddress(&pq, g_q);       cudaGetSymbolAddress(&pk, g_k);
    cudaGetSymbolAddress(&pv, g_v);       cudaGetSymbolAddress(&pskip, g_skip);
    cudaGetSymbolAddress(&pout, g_out);
    cudaGetSymbolAddress(&pxh, g_xh);     cudaGetSymbolAddress(&pxl, g_xl);
    cudaGetSymbolAddress(&pouth, g_outh); cudaGetSymbolAddress(&poutl, g_outl);
    cudaGetSymbolAddress(&ph1h, g_h1h);   cudaGetSymbolAddress(&ph1l, g_h1l);
    cudaGetSymbolAddress(&pw4h, g_w4h);   cudaGetSymbolAddress(&pw4l, g_w4l);
    cudaGetSymbolAddress(&pw1h, g_w1h);   cudaGetSymbolAddress(&pw1l, g_w1l);
    cudaGetSymbolAddress(&pw2h, g_w2h);   cudaGetSymbolAddress(&pw2l, g_w2l);
    cudaGetSymbolAddress(&pb4, g_b4);

    const int SMEM_BIG = 2 * 2 * (ABYTES + BBYTES);
    cudaFuncSetAttribute(wgemm<256,1>, cudaFuncAttributeMaxDynamicSharedMemorySize, SMEM_BIG);
    cudaFuncSetAttribute(wgemm<256,2>, cudaFuncAttributeMaxDynamicSharedMemorySize, SMEM_BIG);
    cudaFuncSetAttribute(wgemm<256,3>, cudaFuncAttributeMaxDynamicSharedMemorySize, SMEM_BIG);

    // 0..2: prep
    init_kernel<<<(NN + 255) / 256, 256>>>();
    cvt_weights<<<(CW_TOT + 255) / 256, 256>>>(Wq, Wk, Wv, Wskip, W1, W2, bq, bk, bv);
    cvt_split<<<(NN * HID + 255) / 256, 256>>>(x, (bf*)pxh, (bf*)pxl, NN * HID);

    // 3: fused QKVS  [NNP x 256] @ [256 x 1024]
    wgemm<256,1><<<dim3(8, NNP / 128), 256, SMEM_BIG>>>(
        (bf*)pxh, (bf*)pxl, (bf*)pw4h, (bf*)pw4l, 1024,
        (const float*)pb4, nullptr,
        (float*)pq, (float*)pk, (float*)pv, (float*)pskip, nullptr, nullptr, NN);

    // 4..6: CSR build (independent of QKVS)
    hist_kernel<<<(EE + 255) / 256, 256>>>(edge_idx);
    scan_kernel<<<1, 1024>>>();
    scatter_kernel<<<(EE + 255) / 256, 256>>>(edge_idx);

    // 7: G = per-head We . q
    g_kernel<<<(NN + 7) / 8, 256>>>(We);

    // 8: fused attention (softmax + aggregate + skip + bf16 split)
    attn_kernel<<<(NN + 7) / 8, 256>>>(edge_idx, edge_attr, We);

    // 9..10: MLP
    wgemm<256,2><<<dim3(2, NNP / 128), 256, SMEM_BIG>>>(
        (bf*)pouth, (bf*)poutl, (bf*)pw1h, (bf*)pw1l, 256,
        b1, nullptr, nullptr, nullptr, nullptr, nullptr,
        (bf*)ph1h, (bf*)ph1l, NN);
    wgemm<256,3><<<dim3(2, NNP / 128), 256, SMEM_BIG>>>(
        (bf*)ph1h, (bf*)ph1l, (bf*)pw2h, (bf*)pw2l, 256,
        b2, (const float*)pout, (float*)d_out, nullptr, nullptr, nullptr,
        nullptr, nullptr, NN);
}

// round 7
// speedup vs baseline: 1.7812x; 1.0789x over previous
#include <cuda_runtime.h>
#include <cuda_bf16.h>
#include <mma.h>
#include <math.h>
#include <cstdint>

using namespace nvcuda;
typedef __nv_bfloat16 bf;

#define NN 30000
#define NNP 30080
#define EE 300000
#define HH 8
#define HID 256

// ===================== PTX helpers ==========================================
__device__ __forceinline__ uint32_t smem_u32(const void* p) {
    uint32_t a;
    asm("{ .reg .u64 t; cvta.to.shared.u64 t, %1; cvt.u32.u64 %0, t; }" : "=r"(a) : "l"(p));
    return a;
}
#define CP_ASYNC16(saddr, gptr) \
    asm volatile("cp.async.cg.shared.global [%0], [%1], 16;" :: "r"(saddr), "l"(gptr))
#define CP_COMMIT() asm volatile("cp.async.commit_group;" ::: "memory")
#define CP_WAIT(n)  asm volatile("cp.async.wait_group %0;" :: "n"(n) : "memory")

// ===================== scratch ==============================================
__device__ float g_q[NN * HID];
__device__ float g_k[NN * HID];
__device__ float g_v[NN * HID];
__device__ float g_skip[NN * HID];
__device__ float g_out[NN * HID];

__device__ int g_deg[NN];
__device__ int g_pos[NN];
__device__ int g_off[NN + 1];
__device__ int g_eid[EE];

__device__ bf g_xh[NNP * HID],   g_xl[NNP * HID];
__device__ bf g_outh[NNP * HID], g_outl[NNP * HID];   // pad rows stay 0
__device__ bf g_h1h[NNP * HID],  g_h1l[NNP * HID];
__device__ bf g_w4h[256 * 1024], g_w4l[256 * 1024];   // [K=256][Wq|Wk|Wv|Wskip]
__device__ bf g_w1h[256 * 256],  g_w1l[256 * 256];
__device__ bf g_w2h[256 * 256],  g_w2l[256 * 256];
__device__ float g_b4[1024];

// ===================== scalar helpers =======================================
__device__ __forceinline__ float gelu_tanh(float x) {
    float x3 = x * x * x;
    float t = tanhf(0.7978845608028654f * (x + 0.044715f * x3));
    return 0.5f * x * (1.0f + t);
}
__device__ __forceinline__ void split2(float v, bf& h, bf& l) {
    h = __float2bfloat16(v);
    l = __float2bfloat16(v - __bfloat162float(h));
}

// ===================== conversion kernels ===================================
__global__ void cvt_split(const float* __restrict__ src, bf* __restrict__ h,
                          bf* __restrict__ l, int n) {
    int i = blockIdx.x * blockDim.x + threadIdx.x;
    if (i >= n) return;
    float v = src[i];
    bf hh = __float2bfloat16(v);
    h[i] = hh;
    l[i] = __float2bfloat16(v - __bfloat162float(hh));
}

#define W4_SZ   (256 * 1024)
#define W1_OFF  W4_SZ
#define W2_OFF  (W1_OFF + 65536)
#define B4_OFF  (W2_OFF + 65536)
#define CW_TOT  (B4_OFF + 1024)

__global__ void cvt_weights(const float* __restrict__ Wq, const float* __restrict__ Wk,
                            const float* __restrict__ Wv, const float* __restrict__ Ws,
                            const float* __restrict__ W1, const float* __restrict__ W2,
                            const float* __restrict__ bq, const float* __restrict__ bk,
                            const float* __restrict__ bv) {
    int i = blockIdx.x * blockDim.x + threadIdx.x;
    if (i < W4_SZ) {
        int k = i >> 10, j = i & 1023, g = j >> 8, n = j & 255;
        const float* W = (g == 0) ? Wq : (g == 1) ? Wk : (g == 2) ? Wv : Ws;
        split2(W[k * 256 + n], g_w4h[i], g_w4l[i]);
    } else if (i < W2_OFF) {
        int t = i - W1_OFF; split2(W1[t], g_w1h[t], g_w1l[t]);
    } else if (i < B4_OFF) {
        int t = i - W2_OFF; split2(W2[t], g_w2h[t], g_w2l[t]);
    } else if (i < CW_TOT) {
        int t = i - B4_OFF, g = t >> 8, n = t & 255;
        g_b4[t] = (g == 0) ? bq[n] : (g == 1) ? bk[n] : (g == 2) ? bv[n] : 0.0f;
    }
}

// ===================== pipelined wmma GEMM (CHUNK=32, 2 CTAs/SM) =============
static constexpr int CHUNK  = 32;
static constexpr int APITCH = CHUNK + 8;            // 40
static constexpr int BPITCH = 136;
static constexpr int ABYTES = 128 * APITCH * 2;     // 10240
static constexpr int BBYTES = CHUNK * BPITCH * 2;   // 8704
static constexpr int BBASE  = 2 * 2 * ABYTES;       // 40960
static constexpr int SMEM_G = 2 * 2 * (ABYTES + BBYTES);  // 75776

__device__ __forceinline__ void prefetch_tiles(
    uint32_t sbase,
    const bf* __restrict__ Ah, const bf* __restrict__ Al,
    const bf* __restrict__ Bh, const bf* __restrict__ Bl,
    int NTOT, int row0, int n0, int c, int buf, int tid)
{
    const bf* Ag[2] = {Ah, Al};
    const bf* Bg[2] = {Bh, Bl};
#pragma unroll
    for (int hl = 0; hl < 2; hl++) {
        uint32_t sA = sbase + (uint32_t)(buf * 2 + hl) * ABYTES;
        const bf* srcA = Ag[hl] + (size_t)row0 * 256 + c * CHUNK;
#pragma unroll
        for (int it = 0; it < 2; it++) {
            int i = tid + it * 256;
            int r = i >> 2, cc = i & 3;
            CP_ASYNC16(sA + r * (APITCH * 2) + cc * 16, srcA + (size_t)r * 256 + cc * 8);
        }
        uint32_t sB = sbase + BBASE + (uint32_t)(buf * 2 + hl) * BBYTES;
        const bf* srcB = Bg[hl] + (size_t)(c * CHUNK) * NTOT + n0;
#pragma unroll
        for (int it = 0; it < 2; it++) {
            int i = tid + it * 256;
            int r = i >> 4, cc = i & 15;
            CP_ASYNC16(sB + r * (BPITCH * 2) + cc * 16, srcB + (size_t)r * NTOT + cc * 8);
        }
    }
}

// EPI: 1 +bias f32 (4-way out split) | 2 +bias,gelu -> bf16 hi/lo | 3 +bias,gelu,+res -> f32
template <int EPI>
__global__ void __launch_bounds__(256, 2) wgemm(
    const bf* __restrict__ Ah, const bf* __restrict__ Al,
    const bf* __restrict__ Bh, const bf* __restrict__ Bl, int NTOT,
    const float* __restrict__ bias, const float* __restrict__ res,
    float* __restrict__ O0, float* __restrict__ O1,
    float* __restrict__ O2, float* __restrict__ O3,
    bf* __restrict__ Ch, bf* __restrict__ Cl, int M)
{
    extern __shared__ char smem[];
    const uint32_t sbase = smem_u32(smem);

    int tid = threadIdx.x;
    int wid = tid >> 5;
    int mw = wid >> 1, nw = wid & 1;
    int n0 = blockIdx.x * 128;
    int row0 = blockIdx.y * 128;

    wmma::fragment<wmma::accumulator, 16, 16, 16, float> acc[2][4];
#pragma unroll
    for (int i = 0; i < 2; i++)
#pragma unroll
        for (int j = 0; j < 4; j++) wmma::fill_fragment(acc[i][j], 0.0f);

    prefetch_tiles(sbase, Ah, Al, Bh, Bl, NTOT, row0, n0, 0, 0, tid);
    CP_COMMIT();

#pragma unroll 1
    for (int c = 0; c < 8; c++) {
        if (c + 1 < 8) {
            prefetch_tiles(sbase, Ah, Al, Bh, Bl, NTOT, row0, n0, c + 1, (c + 1) & 1, tid);
            CP_COMMIT();
            CP_WAIT(1);
        } else {
            CP_WAIT(0);
        }
        __syncthreads();

        int buf = c & 1;
        const bf* sAh = reinterpret_cast<const bf*>(smem + (size_t)(buf * 2 + 0) * ABYTES);
        const bf* sAl = reinterpret_cast<const bf*>(smem + (size_t)(buf * 2 + 1) * ABYTES);
        const bf* sBh = reinterpret_cast<const bf*>(smem + BBASE + (size_t)(buf * 2 + 0) * BBYTES);
        const bf* sBl = reinterpret_cast<const bf*>(smem + BBASE + (size_t)(buf * 2 + 1) * BBYTES);

#pragma unroll
        for (int ks = 0; ks < 2; ks++) {
            wmma::fragment<wmma::matrix_a, 16, 16, 16, bf, wmma::row_major> fah[2], fal[2];
            wmma::load_matrix_sync(fah[0], sAh + (mw * 32) * APITCH + ks * 16, APITCH);
            wmma::load_matrix_sync(fah[1], sAh + (mw * 32 + 16) * APITCH + ks * 16, APITCH);
            wmma::load_matrix_sync(fal[0], sAl + (mw * 32) * APITCH + ks * 16, APITCH);
            wmma::load_matrix_sync(fal[1], sAl + (mw * 32 + 16) * APITCH + ks * 16, APITCH);
#pragma unroll
            for (int j = 0; j < 4; j++) {
                wmma::fragment<wmma::matrix_b, 16, 16, 16, bf, wmma::row_major> fbh, fbl;
                wmma::load_matrix_sync(fbh, sBh + (ks * 16) * BPITCH + nw * 64 + j * 16, BPITCH);
                wmma::load_matrix_sync(fbl, sBl + (ks * 16) * BPITCH + nw * 64 + j * 16, BPITCH);
#pragma unroll
                for (int i = 0; i < 2; i++) {
                    wmma::mma_sync(acc[i][j], fah[i], fbh, acc[i][j]);
                    wmma::mma_sync(acc[i][j], fah[i], fbl, acc[i][j]);
                    wmma::mma_sync(acc[i][j], fal[i], fbh, acc[i][j]);
                }
            }
        }
        __syncthreads();
    }

    // epilogue stage fits in 67,584 B < SMEM_G
    float* stage = reinterpret_cast<float*>(smem);
    {
        int base = (mw * 32) * 132 + nw * 64;
#pragma unroll
        for (int i = 0; i < 2; i++)
#pragma unroll
            for (int j = 0; j < 4; j++)
                wmma::store_matrix_sync(stage + base + i * 16 * 132 + j * 16,
                                        acc[i][j], 132, wmma::mem_row_major);
    }
    __syncthreads();

    float* Of = O0;
    if (EPI != 2) {
        int which = n0 >> 8;
        Of = (which == 0) ? O0 : (which == 1) ? O1 : (which == 2) ? O2 : O3;
    }
    int cb0 = n0 & 255;

    for (int i = tid; i < 128 * 32; i += 256) {
        int r = i >> 5, c4 = i & 31;
        int grow = row0 + r;
        if (grow >= M) continue;
        float4 v = *reinterpret_cast<float4*>(stage + r * 132 + c4 * 4);
        if (EPI >= 1) {
            const float* bp = bias + n0 + c4 * 4;
            v.x += bp[0]; v.y += bp[1]; v.z += bp[2]; v.w += bp[3];
        }
        if (EPI >= 2) {
            v.x = gelu_tanh(v.x); v.y = gelu_tanh(v.y);
            v.z = gelu_tanh(v.z); v.w = gelu_tanh(v.w);
        }
        size_t idx = (size_t)grow * 256 + cb0 + c4 * 4;
        if (EPI == 2) {
            bf h0, l0, h1, l1, h2, l2, h3, l3;
            split2(v.x, h0, l0); split2(v.y, h1, l1);
            split2(v.z, h2, l2); split2(v.w, h3, l3);
            __nv_bfloat162 hh0{h0, h1}, hh1{h2, h3}, ll0{l0, l1}, ll1{l2, l3};
            *reinterpret_cast<__nv_bfloat162*>(Ch + idx)     = hh0;
            *reinterpret_cast<__nv_bfloat162*>(Ch + idx + 2) = hh1;
            *reinterpret_cast<__nv_bfloat162*>(Cl + idx)     = ll0;
            *reinterpret_cast<__nv_bfloat162*>(Cl + idx + 2) = ll1;
        } else {
            if (EPI == 3) {
                float4 rr = *reinterpret_cast<const float4*>(res + idx);
                v.x += rr.x; v.y += rr.y; v.z += rr.z; v.w += rr.w;
            }
            *reinterpret_cast<float4*>(Of + idx) = v;
        }
    }
}

// ===================== CSR build ============================================
__global__ void init_kernel() {
    int i = blockIdx.x * blockDim.x + threadIdx.x;
    if (i < NN) { g_deg[i] = 0; g_pos[i] = 0; }
}
__global__ void hist_kernel(const int* __restrict__ ei) {
    int e = blockIdx.x * blockDim.x + threadIdx.x;
    if (e >= EE) return;
    atomicAdd(&g_deg[ei[EE + e]], 1);
}
__global__ void scan_kernel() {
    __shared__ int s[1024];
    __shared__ int carry;
    int t = threadIdx.x;
    if (t == 0) { carry = 0; g_off[0] = 0; }
    __syncthreads();
    for (int base = 0; base < NN; base += 1024) {
        int i = base + t;
        int v = (i < NN) ? g_deg[i] : 0;
        s[t] = v;
        __syncthreads();
#pragma unroll
        for (int d = 1; d < 1024; d <<= 1) {
            int tmp = (t >= d) ? s[t - d] : 0;
            __syncthreads();
            s[t] += tmp;
            __syncthreads();
        }
        if (i < NN) g_off[i + 1] = s[t] + carry;
        __syncthreads();
        if (t == 1023) carry += s[1023];
        __syncthreads();
    }
}
__global__ void scatter_kernel(const int* __restrict__ ei) {
    int e = blockIdx.x * blockDim.x + threadIdx.x;
    if (e >= EE) return;
    int dst = ei[EE + e];
    int p = atomicAdd(&g_pos[dst], 1);
    g_eid[g_off[dst] + p] = e;
}

// ===================== fused attention: single-pass online softmax ==========
// warp per dst node. G folded in (per-node shfl GEMV against smem We).
__global__ void __launch_bounds__(256) attn_kernel(const int* __restrict__ ei,
                                                   const float* __restrict__ ea,
                                                   const float* __restrict__ We) {
    __shared__ float sWe[32 * 257];
    int tid = threadIdx.x, wid = tid >> 5, lane = tid & 31;
    for (int i = tid; i < 8192; i += 256) {
        int d = i >> 8, j = i & 255;
        sWe[d * 257 + j] = We[i];
    }
    __syncthreads();

    int n = blockIdx.x * 8 + wid;
    if (n >= NN) return;

    float qreg[8];
#pragma unroll
    for (int h = 0; h < 8; h++)
        qreg[h] = g_q[(size_t)n * 256 + h * 32 + lane];

    // G[d=lane][h] = sum_c We[d, h*32+c] * q[h*32+c]
    float Greg[8];
#pragma unroll
    for (int h = 0; h < 8; h++) {
        float a = 0.0f;
#pragma unroll
        for (int c = 0; c < 32; c++) {
            float qc = __shfl_sync(0xffffffffu, qreg[h], c);
            a += sWe[lane * 257 + h * 32 + c] * qc;
        }
        Greg[h] = a;
    }

    int off0 = g_off[n];
    int deg = g_off[n + 1] - off0;
    const float scale = 0.17677669529663687f;  // 1/sqrt(32)

    // each lane tracks running max & denom for head (lane & 7)
    float m1 = -INFINITY, den1 = 0.0f;
    float acc[8], wea[8];
#pragma unroll
    for (int h = 0; h < 8; h++) { acc[h] = 0.0f; wea[h] = 0.0f; }
    int hm = lane & 7;

    for (int i = 0; i < deg; i++) {
        int eid = g_eid[off0 + i];
        int src = ei[eid];
        float ea_l = ea[(size_t)eid * 32 + lane];
        const float* krow = g_k + (size_t)src * 256;
        const float* vrow = g_v + (size_t)src * 256;
        float s[8], vv[8];
#pragma unroll
        for (int h = 0; h < 8; h++) {
            s[h] = qreg[h] * krow[h * 32 + lane] + ea_l * Greg[h];
            vv[h] = vrow[h * 32 + lane];
        }
#pragma unroll
        for (int o = 16; o; o >>= 1)
#pragma unroll
            for (int h = 0; h < 8; h++) s[h] += __shfl_xor_sync(0xffffffffu, s[h], o);

        // select this lane's head logit (all lanes have full s[])
        float sh;
        switch (hm) {
            case 0: sh = s[0]; break;  case 1: sh = s[1]; break;
            case 2: sh = s[2]; break;  case 3: sh = s[3]; break;
            case 4: sh = s[4]; break;  case 5: sh = s[5]; break;
            case 6: sh = s[6]; break;  default: sh = s[7]; break;
        }
        sh *= scale;
        float mnew = fmaxf(m1, sh);
        float corr1 = __expf(m1 - mnew);   // exp(-inf)=0 handles first edge
        float a1 = __expf(sh - mnew);
        den1 = den1 * corr1 + a1;
        m1 = mnew;

        float ch[8], ah[8];
#pragma unroll
        for (int h = 0; h < 8; h++) {
            ch[h] = __shfl_sync(0xffffffffu, corr1, h);
            ah[h] = __shfl_sync(0xffffffffu, a1, h);
        }
#pragma unroll
        for (int h = 0; h < 8; h++) {
            acc[h] = acc[h] * ch[h] + ah[h] * vv[h];
            wea[h] = wea[h] * ch[h] + ah[h] * ea_l;
        }
    }

    float denh[8];
#pragma unroll
    for (int h = 0; h < 8; h++) denh[h] = __shfl_sync(0xffffffffu, den1, h);

    // epilogue: + (wea @ We), divide, skip, write + bf16 split
#pragma unroll
    for (int h = 0; h < 8; h++) {
        float extra = 0.0f;
#pragma unroll
        for (int d = 0; d < 32; d++) {
            float w_hd = __shfl_sync(0xffffffffu, wea[h], d);
            extra += w_hd * sWe[d * 257 + h * 32 + lane];
        }
        size_t idx = (size_t)n * 256 + h * 32 + lane;
        float o = (acc[h] + extra) / (denh[h] + 1e-16f) + g_skip[idx];
        g_out[idx] = o;
        bf oh, ol;
        split2(o, oh, ol);
        g_outh[idx] = oh;
        g_outl[idx] = ol;
    }
}

// ===================== launch ===============================================
extern "C" void kernel_launch(void* const* d_in, const int* in_sizes, int n_in,
                              void* d_out, int out_size) {
    const float* x         = (const float*)d_in[0];
    const int*   edge_idx  = (const int*)d_in[1];
    const float* edge_attr = (const float*)d_in[2];
    const float* Wq = (const float*)d_in[3];
    const float* bq = (const float*)d_in[4];
    const float* Wk = (const float*)d_in[5];
    const float* bk = (const float*)d_in[6];
    const float* Wv = (const float*)d_in[7];
    const float* bv = (const float*)d_in[8];
    const float* We = (const float*)d_in[9];
    const float* Wskip = (const float*)d_in[10];
    const float* W1 = (const float*)d_in[11];
    const float* b1 = (const float*)d_in[12];
    const float* W2 = (const float*)d_in[13];
    const float* b2 = (const float*)d_in[14];

    void *pq, *pk, *pv, *pskip, *pout;
    void *pxh, *pxl, *pouth, *poutl, *ph1h, *ph1l;
    void *pw4h, *pw4l, *pw1h, *pw1l, *pw2h, *pw2l, *pb4;
    cudaGetSymbolAddress(&pq, g_q);       cudaGetSymbolAddress(&pk, g_k);
    cudaGetSymbolAddress(&pv, g_v);       cudaGetSymbolAddress(&pskip, g_skip);
    cudaGetSymbolAddress(&pout, g_out);
    cudaGetSymbolAddress(&pxh, g_xh);     cudaGetSymbolAddress(&pxl, g_xl);
    cudaGetSymbolAddress(&pouth, g_outh); cudaGetSymbolAddress(&poutl, g_outl);
    cudaGetSymbolAddress(&ph1h, g_h1h);   cudaGetSymbolAddress(&ph1l, g_h1l);
    cudaGetSymbolAddress(&pw4h, g_w4h);   cudaGetSymbolAddress(&pw4l, g_w4l);
    cudaGetSymbolAddress(&pw1h, g_w1h);   cudaGetSymbolAddress(&pw1l, g_w1l);
    cudaGetSymbolAddress(&pw2h, g_w2h);   cudaGetSymbolAddress(&pw2l, g_w2l);
    cudaGetSymbolAddress(&pb4, g_b4);

    cudaFuncSetAttribute(wgemm<1>, cudaFuncAttributeMaxDynamicSharedMemorySize, SMEM_G);
    cudaFuncSetAttribute(wgemm<2>, cudaFuncAttributeMaxDynamicSharedMemorySize, SMEM_G);
    cudaFuncSetAttribute(wgemm<3>, cudaFuncAttributeMaxDynamicSharedMemorySize, SMEM_G);

    // 0..2: prep
    init_kernel<<<(NN + 255) / 256, 256>>>();
    cvt_weights<<<(CW_TOT + 255) / 256, 256>>>(Wq, Wk, Wv, Wskip, W1, W2, bq, bk, bv);
    cvt_split<<<(NN * HID + 255) / 256, 256>>>(x, (bf*)pxh, (bf*)pxl, NN * HID);

    // 3: fused QKVS  [NNP x 256] @ [256 x 1024]   (ncu capture slot)
    wgemm<1><<<dim3(8, NNP / 128), 256, SMEM_G>>>(
        (bf*)pxh, (bf*)pxl, (bf*)pw4h, (bf*)pw4l, 1024,
        (const float*)pb4, nullptr,
        (float*)pq, (float*)pk, (float*)pv, (float*)pskip, nullptr, nullptr, NN);

    // 4..6: CSR build
    hist_kernel<<<(EE + 255) / 256, 256>>>(edge_idx);
    scan_kernel<<<1, 1024>>>();
    scatter_kernel<<<(EE + 255) / 256, 256>>>(edge_idx);

    // 7: fused single-pass attention
    attn_kernel<<<(NN + 7) / 8, 256>>>(edge_idx, edge_attr, We);

    // 8..9: MLP
    wgemm<2><<<dim3(2, NNP / 128), 256, SMEM_G>>>(
        (bf*)pouth, (bf*)poutl, (bf*)pw1h, (bf*)pw1l, 256,
        b1, nullptr, nullptr, nullptr, nullptr, nullptr,
        (bf*)ph1h, (bf*)ph1l, NN);
    wgemm<3><<<dim3(2, NNP / 128), 256, SMEM_G>>>(
        (bf*)ph1h, (bf*)ph1l, (bf*)pw2h, (bf*)pw2l, 256,
        b2, (const float*)pout, (float*)d_out, nullptr, nullptr, nullptr,
        nullptr, nullptr, NN);
}

// round 8
// speedup vs baseline: 1.8515x; 1.0395x over previous
#include <cuda_runtime.h>
#include <cuda_bf16.h>
#include <mma.h>
#include <math.h>
#include <cstdint>

using namespace nvcuda;
typedef __nv_bfloat16 bf;

#define NN 30000
#define NNP 30080
#define EE 300000
#define HH 8
#define HID 256
#define NB 118   // ceil(NN/256)

// ===================== PTX helpers ==========================================
__device__ __forceinline__ uint32_t smem_u32(const void* p) {
    uint32_t a;
    asm("{ .reg .u64 t; cvta.to.shared.u64 t, %1; cvt.u32.u64 %0, t; }" : "=r"(a) : "l"(p));
    return a;
}
#define CP_ASYNC16(saddr, gptr) \
    asm volatile("cp.async.cg.shared.global [%0], [%1], 16;" :: "r"(saddr), "l"(gptr))
#define CP_COMMIT() asm volatile("cp.async.commit_group;" ::: "memory")
#define CP_WAIT(n)  asm volatile("cp.async.wait_group %0;" :: "n"(n) : "memory")

// ===================== scratch ==============================================
__device__ float g_q[NN * HID];
__device__ float g_k[NN * HID];
__device__ float g_v[NN * HID];
__device__ float g_skip[NN * HID];
__device__ float g_out[NN * HID];

__device__ int  g_deg[NN];
__device__ int  g_pos[NN];
__device__ int  g_off[NN + 1];
__device__ int  g_tmp[NN];
__device__ int  g_bsum[128];
__device__ int2 g_es[EE];     // (src, eid) per CSR slot

__device__ bf g_xh[NNP * HID],   g_xl[NNP * HID];
__device__ bf g_outh[NNP * HID], g_outl[NNP * HID];   // pad rows stay 0
__device__ bf g_h1h[NNP * HID],  g_h1l[NNP * HID];
__device__ bf g_w4h[256 * 1024], g_w4l[256 * 1024];   // [K=256][Wq|Wk|Wv|Wskip]
__device__ bf g_w1h[256 * 256],  g_w1l[256 * 256];
__device__ bf g_w2h[256 * 256],  g_w2l[256 * 256];

// ===================== scalar helpers =======================================
__device__ __forceinline__ float gelu_tanh(float x) {
    float x3 = x * x * x;
    float t = tanhf(0.7978845608028654f * (x + 0.044715f * x3));
    return 0.5f * x * (1.0f + t);
}
__device__ __forceinline__ void split2(float v, bf& h, bf& l) {
    h = __float2bfloat16(v);
    l = __float2bfloat16(v - __bfloat162float(h));
}

// ===================== conversion kernels ===================================
__global__ void cvt_split(const float* __restrict__ src, bf* __restrict__ h,
                          bf* __restrict__ l, int n) {
    int i = blockIdx.x * blockDim.x + threadIdx.x;
    if (i >= n) return;
    float v = src[i];
    bf hh = __float2bfloat16(v);
    h[i] = hh;
    l[i] = __float2bfloat16(v - __bfloat162float(hh));
}

#define W4_SZ   (256 * 1024)
#define W1_OFF  W4_SZ
#define W2_OFF  (W1_OFF + 65536)
#define CW_TOT  (W2_OFF + 65536)

__global__ void cvt_weights(const float* __restrict__ Wq, const float* __restrict__ Wk,
                            const float* __restrict__ Wv, const float* __restrict__ Ws,
                            const float* __restrict__ W1, const float* __restrict__ W2) {
    int i = blockIdx.x * blockDim.x + threadIdx.x;
    if (i < W4_SZ) {
        int k = i >> 10, j = i & 1023, g = j >> 8, n = j & 255;
        const float* W = (g == 0) ? Wq : (g == 1) ? Wk : (g == 2) ? Wv : Ws;
        split2(W[k * 256 + n], g_w4h[i], g_w4l[i]);
    } else if (i < W2_OFF) {
        int t = i - W1_OFF; split2(W1[t], g_w1h[t], g_w1l[t]);
    } else if (i < CW_TOT) {
        int t = i - W2_OFF; split2(W2[t], g_w2h[t], g_w2l[t]);
    }
}

// ===================== pipelined wmma GEMM (CHUNK=32, 2 CTAs/SM) =============
static constexpr int CHUNK  = 32;
static constexpr int APITCH = CHUNK + 8;            // 40
static constexpr int BPITCH = 136;
static constexpr int ABYTES = 128 * APITCH * 2;     // 10240
static constexpr int BBYTES = CHUNK * BPITCH * 2;   // 8704
static constexpr int BBASE  = 2 * 2 * ABYTES;       // 40960
static constexpr int SMEM_G = 2 * 2 * (ABYTES + BBYTES);  // 75776

__device__ __forceinline__ void prefetch_tiles(
    uint32_t sbase,
    const bf* __restrict__ Ah, const bf* __restrict__ Al,
    const bf* __restrict__ Bh, const bf* __restrict__ Bl,
    int NTOT, int row0, int n0, int c, int buf, int tid)
{
    const bf* Ag[2] = {Ah, Al};
    const bf* Bg[2] = {Bh, Bl};
#pragma unroll
    for (int hl = 0; hl < 2; hl++) {
        uint32_t sA = sbase + (uint32_t)(buf * 2 + hl) * ABYTES;
        const bf* srcA = Ag[hl] + (size_t)row0 * 256 + c * CHUNK;
#pragma unroll
        for (int it = 0; it < 2; it++) {
            int i = tid + it * 256;
            int r = i >> 2, cc = i & 3;
            CP_ASYNC16(sA + r * (APITCH * 2) + cc * 16, srcA + (size_t)r * 256 + cc * 8);
        }
        uint32_t sB = sbase + BBASE + (uint32_t)(buf * 2 + hl) * BBYTES;
        const bf* srcB = Bg[hl] + (size_t)(c * CHUNK) * NTOT + n0;
#pragma unroll
        for (int it = 0; it < 2; it++) {
            int i = tid + it * 256;
            int r = i >> 4, cc = i & 15;
            CP_ASYNC16(sB + r * (BPITCH * 2) + cc * 16, srcB + (size_t)r * NTOT + cc * 8);
        }
    }
}

// EPI: 0 plain f32 (4-way out split) | 2 +bias,gelu -> bf16 hi/lo | 3 +bias,gelu,+res -> f32
template <int EPI>
__global__ void __launch_bounds__(256, 2) wgemm(
    const bf* __restrict__ Ah, const bf* __restrict__ Al,
    const bf* __restrict__ Bh, const bf* __restrict__ Bl, int NTOT,
    const float* __restrict__ bias, const float* __restrict__ res,
    float* __restrict__ O0, float* __restrict__ O1,
    float* __restrict__ O2, float* __restrict__ O3,
    bf* __restrict__ Ch, bf* __restrict__ Cl, int M)
{
    extern __shared__ char smem[];
    const uint32_t sbase = smem_u32(smem);

    int tid = threadIdx.x;
    int wid = tid >> 5;
    int mw = wid >> 1, nw = wid & 1;
    int n0 = blockIdx.x * 128;
    int row0 = blockIdx.y * 128;

    wmma::fragment<wmma::accumulator, 16, 16, 16, float> acc[2][4];
#pragma unroll
    for (int i = 0; i < 2; i++)
#pragma unroll
        for (int j = 0; j < 4; j++) wmma::fill_fragment(acc[i][j], 0.0f);

    prefetch_tiles(sbase, Ah, Al, Bh, Bl, NTOT, row0, n0, 0, 0, tid);
    CP_COMMIT();

#pragma unroll 1
    for (int c = 0; c < 8; c++) {
        if (c + 1 < 8) {
            prefetch_tiles(sbase, Ah, Al, Bh, Bl, NTOT, row0, n0, c + 1, (c + 1) & 1, tid);
            CP_COMMIT();
            CP_WAIT(1);
        } else {
            CP_WAIT(0);
        }
        __syncthreads();

        int buf = c & 1;
        const bf* sAh = reinterpret_cast<const bf*>(smem + (size_t)(buf * 2 + 0) * ABYTES);
        const bf* sAl = reinterpret_cast<const bf*>(smem + (size_t)(buf * 2 + 1) * ABYTES);
        const bf* sBh = reinterpret_cast<const bf*>(smem + BBASE + (size_t)(buf * 2 + 0) * BBYTES);
        const bf* sBl = reinterpret_cast<const bf*>(smem + BBASE + (size_t)(buf * 2 + 1) * BBYTES);

#pragma unroll
        for (int ks = 0; ks < 2; ks++) {
            wmma::fragment<wmma::matrix_a, 16, 16, 16, bf, wmma::row_major> fah[2], fal[2];
            wmma::load_matrix_sync(fah[0], sAh + (mw * 32) * APITCH + ks * 16, APITCH);
            wmma::load_matrix_sync(fah[1], sAh + (mw * 32 + 16) * APITCH + ks * 16, APITCH);
            wmma::load_matrix_sync(fal[0], sAl + (mw * 32) * APITCH + ks * 16, APITCH);
            wmma::load_matrix_sync(fal[1], sAl + (mw * 32 + 16) * APITCH + ks * 16, APITCH);
#pragma unroll
            for (int j = 0; j < 4; j++) {
                wmma::fragment<wmma::matrix_b, 16, 16, 16, bf, wmma::row_major> fbh, fbl;
                wmma::load_matrix_sync(fbh, sBh + (ks * 16) * BPITCH + nw * 64 + j * 16, BPITCH);
                wmma::load_matrix_sync(fbl, sBl + (ks * 16) * BPITCH + nw * 64 + j * 16, BPITCH);
#pragma unroll
                for (int i = 0; i < 2; i++) {
                    wmma::mma_sync(acc[i][j], fah[i], fbh, acc[i][j]);
                    wmma::mma_sync(acc[i][j], fah[i], fbl, acc[i][j]);
                    wmma::mma_sync(acc[i][j], fal[i], fbh, acc[i][j]);
                }
            }
        }
        __syncthreads();
    }

    float* stage = reinterpret_cast<float*>(smem);
    {
        int base = (mw * 32) * 132 + nw * 64;
#pragma unroll
        for (int i = 0; i < 2; i++)
#pragma unroll
            for (int j = 0; j < 4; j++)
                wmma::store_matrix_sync(stage + base + i * 16 * 132 + j * 16,
                                        acc[i][j], 132, wmma::mem_row_major);
    }
    __syncthreads();

    float* Of = O0;
    if (EPI != 2) {
        int which = n0 >> 8;
        Of = (which == 0) ? O0 : (which == 1) ? O1 : (which == 2) ? O2 : O3;
    }
    int cb0 = n0 & 255;

    for (int i = tid; i < 128 * 32; i += 256) {
        int r = i >> 5, c4 = i & 31;
        int grow = row0 + r;
        if (grow >= M) continue;
        float4 v = *reinterpret_cast<float4*>(stage + r * 132 + c4 * 4);
        if (EPI >= 2) {
            const float* bp = bias + c4 * 4;
            v.x = gelu_tanh(v.x + bp[0]); v.y = gelu_tanh(v.y + bp[1]);
            v.z = gelu_tanh(v.z + bp[2]); v.w = gelu_tanh(v.w + bp[3]);
        }
        size_t idx = (size_t)grow * 256 + cb0 + c4 * 4;
        if (EPI == 2) {
            bf h0, l0, h1, l1, h2, l2, h3, l3;
            split2(v.x, h0, l0); split2(v.y, h1, l1);
            split2(v.z, h2, l2); split2(v.w, h3, l3);
            __nv_bfloat162 hh0{h0, h1}, hh1{h2, h3}, ll0{l0, l1}, ll1{l2, l3};
            *reinterpret_cast<__nv_bfloat162*>(Ch + idx)     = hh0;
            *reinterpret_cast<__nv_bfloat162*>(Ch + idx + 2) = hh1;
            *reinterpret_cast<__nv_bfloat162*>(Cl + idx)     = ll0;
            *reinterpret_cast<__nv_bfloat162*>(Cl + idx + 2) = ll1;
        } else {
            if (EPI == 3) {
                float4 rr = *reinterpret_cast<const float4*>(res + idx);
                v.x += rr.x; v.y += rr.y; v.z += rr.z; v.w += rr.w;
            }
            *reinterpret_cast<float4*>(Of + idx) = v;
        }
    }
}

// ===================== CSR build (parallel scan) ============================
__global__ void init_kernel() {
    int i = blockIdx.x * blockDim.x + threadIdx.x;
    if (i < NN) { g_deg[i] = 0; g_pos[i] = 0; }
}
__global__ void hist_kernel(const int* __restrict__ ei) {
    int e = blockIdx.x * blockDim.x + threadIdx.x;
    if (e >= EE) return;
    atomicAdd(&g_deg[ei[EE + e]], 1);
}
__global__ void scan1_kernel() {           // per-block inclusive scan
    __shared__ int s[256];
    int t = threadIdx.x, i = blockIdx.x * 256 + t;
    int v = (i < NN) ? g_deg[i] : 0;
    s[t] = v;
    __syncthreads();
#pragma unroll
    for (int d = 1; d < 256; d <<= 1) {
        int tmp = (t >= d) ? s[t - d] : 0;
        __syncthreads();
        s[t] += tmp;
        __syncthreads();
    }
    if (i < NN) g_tmp[i] = s[t];
    if (t == 255) g_bsum[blockIdx.x] = s[255];
}
__global__ void scan2_kernel() {           // scan 118 block sums
    __shared__ int s[128];
    int t = threadIdx.x;
    s[t] = (t < NB) ? g_bsum[t] : 0;
    __syncthreads();
#pragma unroll
    for (int d = 1; d < 128; d <<= 1) {
        int tmp = (t >= d) ? s[t - d] : 0;
        __syncthreads();
        s[t] += tmp;
        __syncthreads();
    }
    if (t < NB) g_bsum[t] = s[t];
}
__global__ void scan3_kernel() {           // g_off = exclusive prefix
    int i = blockIdx.x * blockDim.x + threadIdx.x;
    if (i == 0) g_off[0] = 0;
    if (i < NN) {
        int b = i >> 8;
        int add = (b > 0) ? g_bsum[b - 1] : 0;
        g_off[i + 1] = g_tmp[i] + add;
    }
}
__global__ void scatter_kernel(const int* __restrict__ ei) {
    int e = blockIdx.x * blockDim.x + threadIdx.x;
    if (e >= EE) return;
    int src = ei[e];
    int dst = ei[EE + e];
    int p = atomicAdd(&g_pos[dst], 1);
    g_es[g_off[dst] + p] = make_int2(src, e);
}

// ===================== fused attention (single-pass, bias-folded) ===========
__global__ void __launch_bounds__(256) attn_kernel(
    const float* __restrict__ ea, const float* __restrict__ We,
    const float* __restrict__ bq, const float* __restrict__ bk,
    const float* __restrict__ bv) {
    __shared__ float sWe[32 * 257];
    int tid = threadIdx.x, wid = tid >> 5, lane = tid & 31;
    for (int i = tid; i < 8192; i += 256) {
        int d = i >> 8, j = i & 255;
        sWe[d * 257 + j] = We[i];
    }
    __syncthreads();

    int n = blockIdx.x * 8 + wid;
    if (n >= NN) return;

    float qreg[8], bkreg[8], bvreg[8];
#pragma unroll
    for (int h = 0; h < 8; h++) {
        qreg[h] = g_q[(size_t)n * 256 + h * 32 + lane] + __ldg(bq + h * 32 + lane);
        bkreg[h] = __ldg(bk + h * 32 + lane);
        bvreg[h] = __ldg(bv + h * 32 + lane);
    }

    // G[d=lane][h] = sum_c We[d, h*32+c] * q[h*32+c]
    float Greg[8];
#pragma unroll
    for (int h = 0; h < 8; h++) {
        float a = 0.0f;
#pragma unroll
        for (int c = 0; c < 32; c++) {
            float qc = __shfl_sync(0xffffffffu, qreg[h], c);
            a += sWe[lane * 257 + h * 32 + c] * qc;
        }
        Greg[h] = a;
    }

    int off0 = g_off[n];
    int deg = g_off[n + 1] - off0;
    const float scale = 0.17677669529663687f;  // 1/sqrt(32)

    float m1 = -INFINITY, den1 = 0.0f;
    float acc[8], wea[8];
#pragma unroll
    for (int h = 0; h < 8; h++) { acc[h] = 0.0f; wea[h] = 0.0f; }
    int hm = lane & 7;

    int2 se_next = (deg > 0) ? g_es[off0] : make_int2(0, 0);
    for (int i = 0; i < deg; i++) {
        int2 se = se_next;
        if (i + 1 < deg) se_next = g_es[off0 + i + 1];
        int src = se.x, eid = se.y;
        float ea_l = ea[(size_t)eid * 32 + lane];
        const float* krow = g_k + (size_t)src * 256;
        const float* vrow = g_v + (size_t)src * 256;
        float s[8], vv[8];
#pragma unroll
        for (int h = 0; h < 8; h++) {
            s[h] = qreg[h] * (krow[h * 32 + lane] + bkreg[h]) + ea_l * Greg[h];
            vv[h] = vrow[h * 32 + lane] + bvreg[h];
        }
#pragma unroll
        for (int o = 16; o; o >>= 1)
#pragma unroll
            for (int h = 0; h < 8; h++) s[h] += __shfl_xor_sync(0xffffffffu, s[h], o);

        float sh;
        switch (hm) {
            case 0: sh = s[0]; break;  case 1: sh = s[1]; break;
            case 2: sh = s[2]; break;  case 3: sh = s[3]; break;
            case 4: sh = s[4]; break;  case 5: sh = s[5]; break;
            case 6: sh = s[6]; break;  default: sh = s[7]; break;
        }
        sh *= scale;
        float mnew = fmaxf(m1, sh);
        float corr1 = __expf(m1 - mnew);
        float a1 = __expf(sh - mnew);
        den1 = den1 * corr1 + a1;
        m1 = mnew;

        float ch[8], ah[8];
#pragma unroll
        for (int h = 0; h < 8; h++) {
            ch[h] = __shfl_sync(0xffffffffu, corr1, h);
            ah[h] = __shfl_sync(0xffffffffu, a1, h);
        }
#pragma unroll
        for (int h = 0; h < 8; h++) {
            acc[h] = acc[h] * ch[h] + ah[h] * vv[h];
            wea[h] = wea[h] * ch[h] + ah[h] * ea_l;
        }
    }

    float denh[8];
#pragma unroll
    for (int h = 0; h < 8; h++) denh[h] = __shfl_sync(0xffffffffu, den1, h);

#pragma unroll
    for (int h = 0; h < 8; h++) {
        float extra = 0.0f;
#pragma unroll
        for (int d = 0; d < 32; d++) {
            float w_hd = __shfl_sync(0xffffffffu, wea[h], d);
            extra += w_hd * sWe[d * 257 + h * 32 + lane];
        }
        size_t idx = (size_t)n * 256 + h * 32 + lane;
        float o = (acc[h] + extra) / (denh[h] + 1e-16f) + g_skip[idx];
        g_out[idx] = o;
        bf oh, ol;
        split2(o, oh, ol);
        g_outh[idx] = oh;
        g_outl[idx] = ol;
    }
}

// ===================== launch ===============================================
extern "C" void kernel_launch(void* const* d_in, const int* in_sizes, int n_in,
                              void* d_out, int out_size) {
    const float* x         = (const float*)d_in[0];
    const int*   edge_idx  = (const int*)d_in[1];
    const float* edge_attr = (const float*)d_in[2];
    const float* Wq = (const float*)d_in[3];
    const float* bq = (const float*)d_in[4];
    const float* Wk = (const float*)d_in[5];
    const float* bk = (const float*)d_in[6];
    const float* Wv = (const float*)d_in[7];
    const float* bv = (const float*)d_in[8];
    const float* We = (const float*)d_in[9];
    const float* Wskip = (const float*)d_in[10];
    const float* W1 = (const float*)d_in[11];
    const float* b1 = (const float*)d_in[12];
    const float* W2 = (const float*)d_in[13];
    const float* b2 = (const float*)d_in[14];

    void *pq, *pk, *pv, *pskip, *pout;
    void *pxh, *pxl, *pouth, *poutl, *ph1h, *ph1l;
    void *pw4h, *pw4l, *pw1h, *pw1l, *pw2h, *pw2l;
    cudaGetSymbolAddress(&pq, g_q);       cudaGetSymbolAddress(&pk, g_k);
    cudaGetSymbolAddress(&pv, g_v);       cudaGetSymbolAddress(&pskip, g_skip);
    cudaGetSymbolAddress(&pout, g_out);
    cudaGetSymbolAddress(&pxh, g_xh);     cudaGetSymbolAddress(&pxl, g_xl);
    cudaGetSymbolAddress(&pouth, g_outh); cudaGetSymbolAddress(&poutl, g_outl);
    cudaGetSymbolAddress(&ph1h, g_h1h);   cudaGetSymbolAddress(&ph1l, g_h1l);
    cudaGetSymbolAddress(&pw4h, g_w4h);   cudaGetSymbolAddress(&pw4l, g_w4l);
    cudaGetSymbolAddress(&pw1h, g_w1h);   cudaGetSymbolAddress(&pw1l, g_w1l);
    cudaGetSymbolAddress(&pw2h, g_w2h);   cudaGetSymbolAddress(&pw2l, g_w2l);

    cudaFuncSetAttribute(wgemm<0>, cudaFuncAttributeMaxDynamicSharedMemorySize, SMEM_G);
    cudaFuncSetAttribute(wgemm<2>, cudaFuncAttributeMaxDynamicSharedMemorySize, SMEM_G);
    cudaFuncSetAttribute(wgemm<3>, cudaFuncAttributeMaxDynamicSharedMemorySize, SMEM_G);

    // persistent side stream + events (created once; host-side only)
    static cudaStream_t s1 = nullptr;
    static cudaEvent_t e0 = nullptr, e1 = nullptr;
    if (s1 == nullptr) {
        cudaStreamCreateWithFlags(&s1, cudaStreamNonBlocking);
        cudaEventCreateWithFlags(&e0, cudaEventDisableTiming);
        cudaEventCreateWithFlags(&e1, cudaEventDisableTiming);
    }

    // main stream: init, conversions, QKVS
    init_kernel<<<(NN + 255) / 256, 256>>>();
    cudaEventRecord(e0, 0);

    // fork: CSR build runs concurrently with conversions + QKVS
    cudaStreamWaitEvent(s1, e0, 0);
    hist_kernel<<<(EE + 255) / 256, 256, 0, s1>>>(edge_idx);
    scan1_kernel<<<NB, 256, 0, s1>>>();
    scan2_kernel<<<1, 128, 0, s1>>>();
    scan3_kernel<<<(NN + 255) / 256, 256, 0, s1>>>();
    scatter_kernel<<<(EE + 255) / 256, 256, 0, s1>>>(edge_idx);
    cudaEventRecord(e1, s1);

    cvt_weights<<<(CW_TOT + 255) / 256, 256>>>(Wq, Wk, Wv, Wskip, W1, W2);
    cvt_split<<<(NN * HID + 255) / 256, 256>>>(x, (bf*)pxh, (bf*)pxl, NN * HID);

    // fused QKVS (no bias — folded into attention)
    wgemm<0><<<dim3(8, NNP / 128), 256, SMEM_G>>>(
        (bf*)pxh, (bf*)pxl, (bf*)pw4h, (bf*)pw4l, 1024,
        nullptr, nullptr,
        (float*)pq, (float*)pk, (float*)pv, (float*)pskip, nullptr, nullptr, NN);

    // join CSR branch, then attention
    cudaStreamWaitEvent(0, e1, 0);
    attn_kernel<<<(NN + 7) / 8, 256>>>(edge_attr, We, bq, bk, bv);

    // MLP
    wgemm<2><<<dim3(2, NNP / 128), 256, SMEM_G>>>(
        (bf*)pouth, (bf*)poutl, (bf*)pw1h, (bf*)pw1l, 256,
        b1, nullptr, nullptr, nullptr, nullptr, nullptr,
        (bf*)ph1h, (bf*)ph1l, NN);
    wgemm<3><<<dim3(2, NNP / 128), 256, SMEM_G>>>(
        (bf*)ph1h, (bf*)ph1l, (bf*)pw2h, (bf*)pw2l, 256,
        b2, (const float*)pout, (float*)d_out, nullptr, nullptr, nullptr,
        nullptr, nullptr, NN);
}

// round 9
// speedup vs baseline: 2.2110x; 1.1942x over previous
#include <cuda_runtime.h>
#include <cuda_bf16.h>
#include <mma.h>
#include <math.h>
#include <cstdint>

using namespace nvcuda;
typedef __nv_bfloat16 bf;

#define NN 30000
#define NNP 30080
#define EE 300000
#define HH 8
#define HID 256
#define NB 118   // ceil(NN/256)

// ===================== PTX helpers ==========================================
__device__ __forceinline__ uint32_t smem_u32(const void* p) {
    uint32_t a;
    asm("{ .reg .u64 t; cvta.to.shared.u64 t, %1; cvt.u32.u64 %0, t; }" : "=r"(a) : "l"(p));
    return a;
}
#define CP_ASYNC16(saddr, gptr) \
    asm volatile("cp.async.cg.shared.global [%0], [%1], 16;" :: "r"(saddr), "l"(gptr))
#define CP_COMMIT() asm volatile("cp.async.commit_group;" ::: "memory")
#define CP_WAIT(n)  asm volatile("cp.async.wait_group %0;" :: "n"(n) : "memory")

// ===================== scratch ==============================================
__device__ float g_q[NN * HID];
__device__ float g_k[NN * HID];
__device__ float g_v[NN * HID];
__device__ float g_skip[NN * HID];
__device__ float g_out[NN * HID];

__device__ int  g_deg[NN];
__device__ int  g_pos[NN];
__device__ int  g_off[NN + 1];
__device__ int  g_tmp[NN];
__device__ int  g_bsum[128];
__device__ int2 g_es[EE];     // (src, eid) per CSR slot

__device__ bf g_xh[NNP * HID],   g_xl[NNP * HID];
__device__ bf g_outh[NNP * HID], g_outl[NNP * HID];   // pad rows stay 0
__device__ bf g_h1h[NNP * HID],  g_h1l[NNP * HID];
__device__ bf g_w4h[256 * 1024], g_w4l[256 * 1024];   // [K=256][Wq|Wk|Wv|Wskip]
__device__ bf g_w1h[256 * 256],  g_w1l[256 * 256];
__device__ bf g_w2h[256 * 256],  g_w2l[256 * 256];

// ===================== scalar helpers =======================================
__device__ __forceinline__ float gelu_tanh(float x) {
    float x3 = x * x * x;
    float t = tanhf(0.7978845608028654f * (x + 0.044715f * x3));
    return 0.5f * x * (1.0f + t);
}
__device__ __forceinline__ void split2(float v, bf& h, bf& l) {
    h = __float2bfloat16(v);
    l = __float2bfloat16(v - __bfloat162float(h));
}

// ===================== conversion kernels ===================================
__global__ void cvt_split(const float* __restrict__ src, bf* __restrict__ h,
                          bf* __restrict__ l, int n) {
    int i = blockIdx.x * blockDim.x + threadIdx.x;
    if (i >= n) return;
    float v = src[i];
    bf hh = __float2bfloat16(v);
    h[i] = hh;
    l[i] = __float2bfloat16(v - __bfloat162float(hh));
}

#define W4_SZ   (256 * 1024)
#define W1_OFF  W4_SZ
#define W2_OFF  (W1_OFF + 65536)
#define CW_TOT  (W2_OFF + 65536)

__global__ void cvt_weights(const float* __restrict__ Wq, const float* __restrict__ Wk,
                            const float* __restrict__ Wv, const float* __restrict__ Ws,
                            const float* __restrict__ W1, const float* __restrict__ W2) {
    int i = blockIdx.x * blockDim.x + threadIdx.x;
    if (i < W4_SZ) {
        int k = i >> 10, j = i & 1023, g = j >> 8, n = j & 255;
        const float* W = (g == 0) ? Wq : (g == 1) ? Wk : (g == 2) ? Wv : Ws;
        split2(W[k * 256 + n], g_w4h[i], g_w4l[i]);
    } else if (i < W2_OFF) {
        int t = i - W1_OFF; split2(W1[t], g_w1h[t], g_w1l[t]);
    } else if (i < CW_TOT) {
        int t = i - W2_OFF; split2(W2[t], g_w2h[t], g_w2l[t]);
    }
}

// ===================== pipelined wmma GEMM (CHUNK=32, 2 CTAs/SM) =============
static constexpr int CHUNK  = 32;
static constexpr int APITCH = CHUNK + 8;            // 40
static constexpr int BPITCH = 136;
static constexpr int ABYTES = 128 * APITCH * 2;     // 10240
static constexpr int BBYTES = CHUNK * BPITCH * 2;   // 8704
static constexpr int BBASE  = 2 * 2 * ABYTES;       // 40960
static constexpr int SMEM_G = 2 * 2 * (ABYTES + BBYTES);  // 75776

__device__ __forceinline__ void prefetch_tiles(
    uint32_t sbase,
    const bf* __restrict__ Ah, const bf* __restrict__ Al,
    const bf* __restrict__ Bh, const bf* __restrict__ Bl,
    int NTOT, int row0, int n0, int c, int buf, int tid)
{
    const bf* Ag[2] = {Ah, Al};
    const bf* Bg[2] = {Bh, Bl};
#pragma unroll
    for (int hl = 0; hl < 2; hl++) {
        uint32_t sA = sbase + (uint32_t)(buf * 2 + hl) * ABYTES;
        const bf* srcA = Ag[hl] + (size_t)row0 * 256 + c * CHUNK;
#pragma unroll
        for (int it = 0; it < 2; it++) {
            int i = tid + it * 256;
            int r = i >> 2, cc = i & 3;
            CP_ASYNC16(sA + r * (APITCH * 2) + cc * 16, srcA + (size_t)r * 256 + cc * 8);
        }
        uint32_t sB = sbase + BBASE + (uint32_t)(buf * 2 + hl) * BBYTES;
        const bf* srcB = Bg[hl] + (size_t)(c * CHUNK) * NTOT + n0;
#pragma unroll
        for (int it = 0; it < 2; it++) {
            int i = tid + it * 256;
            int r = i >> 4, cc = i & 15;
            CP_ASYNC16(sB + r * (BPITCH * 2) + cc * 16, srcB + (size_t)r * NTOT + cc * 8);
        }
    }
}

// EPI: 0 plain f32 (4-way out split) | 2 +bias,gelu -> bf16 hi/lo | 3 +bias,gelu,+res -> f32
template <int EPI>
__global__ void __launch_bounds__(256, 2) wgemm(
    const bf* __restrict__ Ah, const bf* __restrict__ Al,
    const bf* __restrict__ Bh, const bf* __restrict__ Bl, int NTOT,
    const float* __restrict__ bias, const float* __restrict__ res,
    float* __restrict__ O0, float* __restrict__ O1,
    float* __restrict__ O2, float* __restrict__ O3,
    bf* __restrict__ Ch, bf* __restrict__ Cl, int M)
{
    extern __shared__ char smem[];
    const uint32_t sbase = smem_u32(smem);

    int tid = threadIdx.x;
    int wid = tid >> 5;
    int mw = wid >> 1, nw = wid & 1;
    int n0 = blockIdx.x * 128;
    int row0 = blockIdx.y * 128;

    wmma::fragment<wmma::accumulator, 16, 16, 16, float> acc[2][4];
#pragma unroll
    for (int i = 0; i < 2; i++)
#pragma unroll
        for (int j = 0; j < 4; j++) wmma::fill_fragment(acc[i][j], 0.0f);

    prefetch_tiles(sbase, Ah, Al, Bh, Bl, NTOT, row0, n0, 0, 0, tid);
    CP_COMMIT();

#pragma unroll 1
    for (int c = 0; c < 8; c++) {
        if (c + 1 < 8) {
            prefetch_tiles(sbase, Ah, Al, Bh, Bl, NTOT, row0, n0, c + 1, (c + 1) & 1, tid);
            CP_COMMIT();
            CP_WAIT(1);
        } else {
            CP_WAIT(0);
        }
        __syncthreads();

        int buf = c & 1;
        const bf* sAh = reinterpret_cast<const bf*>(smem + (size_t)(buf * 2 + 0) * ABYTES);
        const bf* sAl = reinterpret_cast<const bf*>(smem + (size_t)(buf * 2 + 1) * ABYTES);
        const bf* sBh = reinterpret_cast<const bf*>(smem + BBASE + (size_t)(buf * 2 + 0) * BBYTES);
        const bf* sBl = reinterpret_cast<const bf*>(smem + BBASE + (size_t)(buf * 2 + 1) * BBYTES);

#pragma unroll
        for (int ks = 0; ks < 2; ks++) {
            wmma::fragment<wmma::matrix_a, 16, 16, 16, bf, wmma::row_major> fah[2], fal[2];
            wmma::load_matrix_sync(fah[0], sAh + (mw * 32) * APITCH + ks * 16, APITCH);
            wmma::load_matrix_sync(fah[1], sAh + (mw * 32 + 16) * APITCH + ks * 16, APITCH);
            wmma::load_matrix_sync(fal[0], sAl + (mw * 32) * APITCH + ks * 16, APITCH);
            wmma::load_matrix_sync(fal[1], sAl + (mw * 32 + 16) * APITCH + ks * 16, APITCH);
#pragma unroll
            for (int j = 0; j < 4; j++) {
                wmma::fragment<wmma::matrix_b, 16, 16, 16, bf, wmma::row_major> fbh, fbl;
                wmma::load_matrix_sync(fbh, sBh + (ks * 16) * BPITCH + nw * 64 + j * 16, BPITCH);
                wmma::load_matrix_sync(fbl, sBl + (ks * 16) * BPITCH + nw * 64 + j * 16, BPITCH);
#pragma unroll
                for (int i = 0; i < 2; i++) {
                    wmma::mma_sync(acc[i][j], fah[i], fbh, acc[i][j]);
                    wmma::mma_sync(acc[i][j], fah[i], fbl, acc[i][j]);
                    wmma::mma_sync(acc[i][j], fal[i], fbh, acc[i][j]);
                }
            }
        }
        __syncthreads();
    }

    float* stage = reinterpret_cast<float*>(smem);
    {
        int base = (mw * 32) * 132 + nw * 64;
#pragma unroll
        for (int i = 0; i < 2; i++)
#pragma unroll
            for (int j = 0; j < 4; j++)
                wmma::store_matrix_sync(stage + base + i * 16 * 132 + j * 16,
                                        acc[i][j], 132, wmma::mem_row_major);
    }
    __syncthreads();

    float* Of = O0;
    if (EPI != 2) {
        int which = n0 >> 8;
        Of = (which == 0) ? O0 : (which == 1) ? O1 : (which == 2) ? O2 : O3;
    }
    int cb0 = n0 & 255;

    for (int i = tid; i < 128 * 32; i += 256) {
        int r = i >> 5, c4 = i & 31;
        int grow = row0 + r;
        if (grow >= M) continue;
        float4 v = *reinterpret_cast<float4*>(stage + r * 132 + c4 * 4);
        if (EPI >= 2) {
            const float* bp = bias + c4 * 4;
            v.x = gelu_tanh(v.x + bp[0]); v.y = gelu_tanh(v.y + bp[1]);
            v.z = gelu_tanh(v.z + bp[2]); v.w = gelu_tanh(v.w + bp[3]);
        }
        size_t idx = (size_t)grow * 256 + cb0 + c4 * 4;
        if (EPI == 2) {
            bf h0, l0, h1, l1, h2, l2, h3, l3;
            split2(v.x, h0, l0); split2(v.y, h1, l1);
            split2(v.z, h2, l2); split2(v.w, h3, l3);
            __nv_bfloat162 hh0{h0, h1}, hh1{h2, h3}, ll0{l0, l1}, ll1{l2, l3};
            *reinterpret_cast<__nv_bfloat162*>(Ch + idx)     = hh0;
            *reinterpret_cast<__nv_bfloat162*>(Ch + idx + 2) = hh1;
            *reinterpret_cast<__nv_bfloat162*>(Cl + idx)     = ll0;
            *reinterpret_cast<__nv_bfloat162*>(Cl + idx + 2) = ll1;
        } else {
            if (EPI == 3) {
                float4 rr = *reinterpret_cast<const float4*>(res + idx);
                v.x += rr.x; v.y += rr.y; v.z += rr.z; v.w += rr.w;
            }
            *reinterpret_cast<float4*>(Of + idx) = v;
        }
    }
}

// ===================== CSR build (parallel scan) ============================
__global__ void init_kernel() {
    int i = blockIdx.x * blockDim.x + threadIdx.x;
    if (i < NN) { g_deg[i] = 0; g_pos[i] = 0; }
}
__global__ void hist_kernel(const int* __restrict__ ei) {
    int e = blockIdx.x * blockDim.x + threadIdx.x;
    if (e >= EE) return;
    atomicAdd(&g_deg[ei[EE + e]], 1);
}
__global__ void scan1_kernel() {
    __shared__ int s[256];
    int t = threadIdx.x, i = blockIdx.x * 256 + t;
    int v = (i < NN) ? g_deg[i] : 0;
    s[t] = v;
    __syncthreads();
#pragma unroll
    for (int d = 1; d < 256; d <<= 1) {
        int tmp = (t >= d) ? s[t - d] : 0;
        __syncthreads();
        s[t] += tmp;
        __syncthreads();
    }
    if (i < NN) g_tmp[i] = s[t];
    if (t == 255) g_bsum[blockIdx.x] = s[255];
}
__global__ void scan2_kernel() {
    __shared__ int s[128];
    int t = threadIdx.x;
    s[t] = (t < NB) ? g_bsum[t] : 0;
    __syncthreads();
#pragma unroll
    for (int d = 1; d < 128; d <<= 1) {
        int tmp = (t >= d) ? s[t - d] : 0;
        __syncthreads();
        s[t] += tmp;
        __syncthreads();
    }
    if (t < NB) g_bsum[t] = s[t];
}
__global__ void scan3_kernel() {
    int i = blockIdx.x * blockDim.x + threadIdx.x;
    if (i == 0) g_off[0] = 0;
    if (i < NN) {
        int b = i >> 8;
        int add = (b > 0) ? g_bsum[b - 1] : 0;
        g_off[i + 1] = g_tmp[i] + add;
    }
}
__global__ void scatter_kernel(const int* __restrict__ ei) {
    int e = blockIdx.x * blockDim.x + threadIdx.x;
    if (e >= EE) return;
    int src = ei[e];
    int dst = ei[EE + e];
    int p = atomicAdd(&g_pos[dst], 1);
    g_es[g_off[dst] + p] = make_int2(src, e);
}

// ===================== fused attention (4 lanes/head layout) ================
// lane L: head h = L>>2, sub = L&3, owns output cols [L*8, L*8+8).
// smem: sWe [32][258] (pitch 258, even, conflict-light)
//       per warp: sG [32*9] (G[d*9+h]) + buf [8*34] (q stage / wea / extra)
static constexpr int WE_PITCH = 258;
static constexpr int WS_FLOATS = 288 + 272;     // sG + buf
static constexpr int ATTN_SMEM = (32 * WE_PITCH + 8 * WS_FLOATS) * 4;  // 50944

__global__ void __launch_bounds__(256, 2) attn_kernel(
    const float* __restrict__ ea, const float* __restrict__ We,
    const float* __restrict__ bq, const float* __restrict__ bk,
    const float* __restrict__ bv)
{
    extern __shared__ float sm[];
    float* sWe = sm;
    int tid = threadIdx.x, wid = tid >> 5, lane = tid & 31;
    float* sG  = sm + 32 * WE_PITCH + wid * WS_FLOATS;   // [d*9+h], 288
    float* buf = sG + 288;                               // [h*34 + *], 272

    for (int i = tid; i < 8192; i += 256) {
        int d = i >> 8, col = i & 255;
        sWe[d * WE_PITCH + col] = We[i];
    }
    __syncthreads();

    int n = blockIdx.x * 8 + wid;   // grid exactly covers NN
    const float* qrow = g_q + (size_t)n * 256;

    // ---- phase 1: q (+bq) old-layout -> buf; G[d][h] -> sG ----
#pragma unroll
    for (int h2 = 0; h2 < 8; h2++)
        buf[h2 * 34 + lane] = qrow[h2 * 32 + lane] + __ldg(bq + h2 * 32 + lane);
    __syncwarp();
#pragma unroll
    for (int h2 = 0; h2 < 8; h2++) {
        float g = 0.0f;
#pragma unroll
        for (int c = 0; c < 32; c += 2) {
            float2 w2 = *reinterpret_cast<const float2*>(sWe + lane * WE_PITCH + h2 * 32 + c);
            float2 q2 = *reinterpret_cast<const float2*>(buf + h2 * 34 + c);
            g += w2.x * q2.x + w2.y * q2.y;
        }
        sG[lane * 9 + h2] = g;
    }
    __syncwarp();

    // ---- phase 2: new layout regs ----
    int h = lane >> 2, sub = lane & 3;
    int cbase = lane * 8;
    float Gr[8], qn[8], bkr[8], bvr[8];
#pragma unroll
    for (int j = 0; j < 8; j++)
        Gr[j] = sG[(sub * 8 + j) * 9 + h];
    {
        float4 q0 = *reinterpret_cast<const float4*>(qrow + cbase);
        float4 q1 = *reinterpret_cast<const float4*>(qrow + cbase + 4);
        float4 b0 = __ldg(reinterpret_cast<const float4*>(bq + cbase));
        float4 b1 = __ldg(reinterpret_cast<const float4*>(bq + cbase + 4));
        qn[0] = q0.x + b0.x; qn[1] = q0.y + b0.y; qn[2] = q0.z + b0.z; qn[3] = q0.w + b0.w;
        qn[4] = q1.x + b1.x; qn[5] = q1.y + b1.y; qn[6] = q1.z + b1.z; qn[7] = q1.w + b1.w;
        float4 k0 = __ldg(reinterpret_cast<const float4*>(bk + cbase));
        float4 k1 = __ldg(reinterpret_cast<const float4*>(bk + cbase + 4));
        bkr[0] = k0.x; bkr[1] = k0.y; bkr[2] = k0.z; bkr[3] = k0.w;
        bkr[4] = k1.x; bkr[5] = k1.y; bkr[6] = k1.z; bkr[7] = k1.w;
        float4 v0 = __ldg(reinterpret_cast<const float4*>(bv + cbase));
        float4 v1 = __ldg(reinterpret_cast<const float4*>(bv + cbase + 4));
        bvr[0] = v0.x; bvr[1] = v0.y; bvr[2] = v0.z; bvr[3] = v0.w;
        bvr[4] = v1.x; bvr[5] = v1.y; bvr[6] = v1.z; bvr[7] = v1.w;
    }

    int off0 = g_off[n];
    int deg = g_off[n + 1] - off0;
    const float scale = 0.17677669529663687f;

    float m1 = -INFINITY, den = 0.0f;
    float acc[8], wea[8];
#pragma unroll
    for (int j = 0; j < 8; j++) { acc[j] = 0.0f; wea[j] = 0.0f; }

    int2 se_next = (deg > 0) ? __ldg(reinterpret_cast<const int2*>(g_es) + off0)
                             : make_int2(0, 0);
    for (int i = 0; i < deg; i++) {
        int2 se = se_next;
        if (i + 1 < deg)
            se_next = __ldg(reinterpret_cast<const int2*>(g_es) + off0 + i + 1);
        const float* krow = g_k + (size_t)se.x * 256 + cbase;
        const float* vrow = g_v + (size_t)se.x * 256 + cbase;
        const float* erow = ea + (size_t)se.y * 32 + sub * 8;
        float4 k0 = *reinterpret_cast<const float4*>(krow);
        float4 k1 = *reinterpret_cast<const float4*>(krow + 4);
        float4 v0 = *reinterpret_cast<const float4*>(vrow);
        float4 v1 = *reinterpret_cast<const float4*>(vrow + 4);
        float4 e0 = __ldg(reinterpret_cast<const float4*>(erow));
        float4 e1 = __ldg(reinterpret_cast<const float4*>(erow + 4));
        float kk[8] = {k0.x, k0.y, k0.z, k0.w, k1.x, k1.y, k1.z, k1.w};
        float vv[8] = {v0.x, v0.y, v0.z, v0.w, v1.x, v1.y, v1.z, v1.w};
        float ee[8] = {e0.x, e0.y, e0.z, e0.w, e1.x, e1.y, e1.z, e1.w};

        float s = 0.0f;
#pragma unroll
        for (int j = 0; j < 8; j++) s += qn[j] * (kk[j] + bkr[j]);
#pragma unroll
        for (int j = 0; j < 8; j++) s += ee[j] * Gr[j];
        s += __shfl_xor_sync(0xffffffffu, s, 1);
        s += __shfl_xor_sync(0xffffffffu, s, 2);
        s *= scale;

        float mnew = fmaxf(m1, s);
        float corr = __expf(m1 - mnew);
        float a = __expf(s - mnew);
        den = den * corr + a;
        m1 = mnew;
#pragma unroll
        for (int j = 0; j < 8; j++) {
            acc[j] = acc[j] * corr + a * (vv[j] + bvr[j]);
            wea[j] = wea[j] * corr + a * ee[j];
        }
    }

    // ---- phase 3: epilogue via smem staging ----
#pragma unroll
    for (int j = 0; j < 8; j++)
        buf[h * 34 + sub * 8 + j] = wea[j];
    if (sub == 0) sG[h] = den;      // sG reusable now
    __syncwarp();

#pragma unroll 1
    for (int h2 = 0; h2 < 8; h2++) {
        float e = 0.0f;
#pragma unroll
        for (int d = 0; d < 32; d += 2) {
            float2 w2 = *reinterpret_cast<const float2*>(buf + h2 * 34 + d);
            e += w2.x * sWe[d * WE_PITCH + h2 * 32 + lane]
               + w2.y * sWe[(d + 1) * WE_PITCH + h2 * 32 + lane];
        }
        __syncwarp();
        buf[h2 * 34 + lane] = e;    // overwrite wea row h2 after all lanes read it
    }
    __syncwarp();

    float den_h = sG[h];
    float inv = 1.0f / (den_h + 1e-16f);
    const float* skiprow = g_skip + (size_t)n * 256 + cbase;
    float4 s0 = *reinterpret_cast<const float4*>(skiprow);
    float4 s1 = *reinterpret_cast<const float4*>(skiprow + 4);
    float sk[8] = {s0.x, s0.y, s0.z, s0.w, s1.x, s1.y, s1.z, s1.w};

    float o[8];
#pragma unroll
    for (int j = 0; j < 8; j++) {
        float ex = buf[h * 34 + sub * 8 + j];
        o[j] = (acc[j] + ex) * inv + sk[j];
    }
    size_t obase = (size_t)n * 256 + cbase;
    *reinterpret_cast<float4*>(g_out + obase)     = make_float4(o[0], o[1], o[2], o[3]);
    *reinterpret_cast<float4*>(g_out + obase + 4) = make_float4(o[4], o[5], o[6], o[7]);
    bf oh[8], ol[8];
#pragma unroll
    for (int j = 0; j < 8; j++) split2(o[j], oh[j], ol[j]);
    *reinterpret_cast<uint4*>(g_outh + obase) = *reinterpret_cast<uint4*>(oh);
    *reinterpret_cast<uint4*>(g_outl + obase) = *reinterpret_cast<uint4*>(ol);
}

// ===================== launch ===============================================
extern "C" void kernel_launch(void* const* d_in, const int* in_sizes, int n_in,
                              void* d_out, int out_size) {
    const float* x         = (const float*)d_in[0];
    const int*   edge_idx  = (const int*)d_in[1];
    const float* edge_attr = (const float*)d_in[2];
    const float* Wq = (const float*)d_in[3];
    const float* bq = (const float*)d_in[4];
    const float* Wk = (const float*)d_in[5];
    const float* bk = (const float*)d_in[6];
    const float* Wv = (const float*)d_in[7];
    const float* bv = (const float*)d_in[8];
    const float* We = (const float*)d_in[9];
    const float* Wskip = (const float*)d_in[10];
    const float* W1 = (const float*)d_in[11];
    const float* b1 = (const float*)d_in[12];
    const float* W2 = (const float*)d_in[13];
    const float* b2 = (const float*)d_in[14];

    void *pq, *pk, *pv, *pskip, *pout;
    void *pxh, *pxl, *pouth, *poutl, *ph1h, *ph1l;
    void *pw4h, *pw4l, *pw1h, *pw1l, *pw2h, *pw2l;
    cudaGetSymbolAddress(&pq, g_q);       cudaGetSymbolAddress(&pk, g_k);
    cudaGetSymbolAddress(&pv, g_v);       cudaGetSymbolAddress(&pskip, g_skip);
    cudaGetSymbolAddress(&pout, g_out);
    cudaGetSymbolAddress(&pxh, g_xh);     cudaGetSymbolAddress(&pxl, g_xl);
    cudaGetSymbolAddress(&pouth, g_outh); cudaGetSymbolAddress(&poutl, g_outl);
    cudaGetSymbolAddress(&ph1h, g_h1h);   cudaGetSymbolAddress(&ph1l, g_h1l);
    cudaGetSymbolAddress(&pw4h, g_w4h);   cudaGetSymbolAddress(&pw4l, g_w4l);
    cudaGetSymbolAddress(&pw1h, g_w1h);   cudaGetSymbolAddress(&pw1l, g_w1l);
    cudaGetSymbolAddress(&pw2h, g_w2h);   cudaGetSymbolAddress(&pw2l, g_w2l);

    cudaFuncSetAttribute(wgemm<0>, cudaFuncAttributeMaxDynamicSharedMemorySize, SMEM_G);
    cudaFuncSetAttribute(wgemm<2>, cudaFuncAttributeMaxDynamicSharedMemorySize, SMEM_G);
    cudaFuncSetAttribute(wgemm<3>, cudaFuncAttributeMaxDynamicSharedMemorySize, SMEM_G);
    cudaFuncSetAttribute(attn_kernel, cudaFuncAttributeMaxDynamicSharedMemorySize, ATTN_SMEM);

    static cudaStream_t s1 = nullptr;
    static cudaEvent_t e0 = nullptr, e1 = nullptr;
    if (s1 == nullptr) {
        cudaStreamCreateWithFlags(&s1, cudaStreamNonBlocking);
        cudaEventCreateWithFlags(&e0, cudaEventDisableTiming);
        cudaEventCreateWithFlags(&e1, cudaEventDisableTiming);
    }

    init_kernel<<<(NN + 255) / 256, 256>>>();
    cudaEventRecord(e0, 0);

    // fork: CSR build overlaps conversions + QKVS
    cudaStreamWaitEvent(s1, e0, 0);
    hist_kernel<<<(EE + 255) / 256, 256, 0, s1>>>(edge_idx);
    scan1_kernel<<<NB, 256, 0, s1>>>();
    scan2_kernel<<<1, 128, 0, s1>>>();
    scan3_kernel<<<(NN + 255) / 256, 256, 0, s1>>>();
    scatter_kernel<<<(EE + 255) / 256, 256, 0, s1>>>(edge_idx);
    cudaEventRecord(e1, s1);

    cvt_weights<<<(CW_TOT + 255) / 256, 256>>>(Wq, Wk, Wv, Wskip, W1, W2);
    cvt_split<<<(NN * HID + 255) / 256, 256>>>(x, (bf*)pxh, (bf*)pxl, NN * HID);

    wgemm<0><<<dim3(8, NNP / 128), 256, SMEM_G>>>(
        (bf*)pxh, (bf*)pxl, (bf*)pw4h, (bf*)pw4l, 1024,
        nullptr, nullptr,
        (float*)pq, (float*)pk, (float*)pv, (float*)pskip, nullptr, nullptr, NN);

    cudaStreamWaitEvent(0, e1, 0);
    attn_kernel<<<NN / 8, 256, ATTN_SMEM>>>(edge_attr, We, bq, bk, bv);

    wgemm<2><<<dim3(2, NNP / 128), 256, SMEM_G>>>(
        (bf*)pouth, (bf*)poutl, (bf*)pw1h, (bf*)pw1l, 256,
        b1, nullptr, nullptr, nullptr, nullptr, nullptr,
        (bf*)ph1h, (bf*)ph1l, NN);
    wgemm<3><<<dim3(2, NNP / 128), 256, SMEM_G>>>(
        (bf*)ph1h, (bf*)ph1l, (bf*)pw2h, (bf*)pw2l, 256,
        b2, (const float*)pout, (float*)d_out, nullptr, nullptr, nullptr,
        nullptr, nullptr, NN);
}